// round 6
// baseline (speedup 1.0000x reference)
#include <cuda_runtime.h>
#include <math.h>
#include <stdint.h>

// Problem constants
#define BB 4
#define SS 2048
#define DD 1024
#define HH 16
#define DKH 64
#define MTOT (BB*SS)          // 8192 rows

// ---------------- scratch (static device globals; no allocation) -------------
__device__ float g_Q [MTOT*DD];
__device__ float g_K [MTOT*DD];
__device__ float g_V [MTOT*DD];
__device__ float g_AO[MTOT*DD];
__device__ float g_Wq[DD*DD];   // tf32-rounded weights
__device__ float g_Wk[DD*DD];
__device__ float g_Wv[DD*DD];
__device__ float g_Wo[DD*DD];

// ---------------- helpers -----------------------------------------------------
__device__ __forceinline__ float tf32r(float x) {
    uint32_t u;
    asm("cvt.rna.tf32.f32 %0, %1;" : "=r"(u) : "f"(x));
    return __uint_as_float(u);
}
__device__ __forceinline__ uint32_t tf32u(float x) {
    uint32_t u;
    asm("cvt.rna.tf32.f32 %0, %1;" : "=r"(u) : "f"(x));
    return u;
}
__device__ __forceinline__ void cpa16(uint32_t smem, const void* gmem) {
    asm volatile("cp.async.cg.shared.global [%0], [%1], 16;" :: "r"(smem), "l"(gmem));
}
__device__ __forceinline__ void cpa_commit() {
    asm volatile("cp.async.commit_group;");
}
template<int N> __device__ __forceinline__ void cpa_wait() {
    asm volatile("cp.async.wait_group %0;" :: "n"(N));
}
__device__ __forceinline__ uint32_t smem_u32(const void* p) {
    uint32_t a;
    asm("{ .reg .u64 t; cvta.to.shared.u64 t, %1; cvt.u32.u64 %0, t; }"
        : "=r"(a) : "l"(p));
    return a;
}
__device__ __forceinline__ void mma_tf32(
    float c[4], const uint32_t a[4], const uint32_t b[2])
{
    asm volatile(
        "mma.sync.aligned.m16n8k8.row.col.f32.tf32.tf32.f32 "
        "{%0,%1,%2,%3}, {%4,%5,%6,%7}, {%8,%9}, {%0,%1,%2,%3};"
        : "+f"(c[0]), "+f"(c[1]), "+f"(c[2]), "+f"(c[3])
        : "r"(a[0]), "r"(a[1]), "r"(a[2]), "r"(a[3]),
          "r"(b[0]), "r"(b[1]));
}

// ---------------- weight rounding prepass ------------------------------------
__global__ __launch_bounds__(256) void round_tf32_kernel(
    const float* __restrict__ in, float* __restrict__ out, int n4)
{
    int i = blockIdx.x * blockDim.x + threadIdx.x;
    if (i < n4) {
        float4 v = ((const float4*)in)[i];
        v.x = tf32r(v.x); v.y = tf32r(v.y);
        v.z = tf32r(v.z); v.w = tf32r(v.w);
        ((float4*)out)[i] = v;
    }
}

// =============================================================================
// TF32 HMMA GEMM v3: C[M,N]=A[M,K]@W[K,N]+bias. Block tile 128x128, K-tile 64,
// 256 threads (8 warps, warp tile 32x64), 3-stage cp.async ring (209 KB smem,
// 1 CTA/SM), ONE __syncthreads per K-iteration, 128 MMAs/warp between barriers.
// =============================================================================
#define GKT 64
#define GAPI 68
#define GBPI 136
#define G_ASZ (128 * GAPI)
#define G_BSZ (GKT * GBPI)
#define G_STG (G_ASZ + G_BSZ)
#define G_SMEM (3 * G_STG * 4)      // 208896 bytes
#define GNT (DD / GKT)              // 16 K-iterations

__global__ __launch_bounds__(256) void gemm_hmma(
    const float* __restrict__ A, const float* __restrict__ W,
    const float* __restrict__ bias, float* __restrict__ C)
{
    extern __shared__ float sh[];

    const int tid  = threadIdx.x;
    const int wid  = tid >> 5;
    const int lane = tid & 31;
    const int g    = lane >> 2;
    const int t    = lane & 3;
    const int wm   = (wid & 3) << 5;
    const int wn   = (wid >> 2) << 6;
    const int m0   = blockIdx.y << 7;
    const int n0   = blockIdx.x << 7;

    float c[2][8][4];
#pragma unroll
    for (int mi = 0; mi < 2; mi++)
#pragma unroll
        for (int ni = 0; ni < 8; ni++)
#pragma unroll
            for (int j = 0; j < 4; j++) c[mi][ni][j] = 0.f;

    const uint32_t shbase = smem_u32(sh);

    auto load_tile = [&](int kt, int stg) {
        const int k0 = kt * GKT;
        const uint32_t sa = shbase + (stg * G_STG) * 4;
        const uint32_t sb = sa + G_ASZ * 4;
#pragma unroll
        for (int j = 0; j < 8; j++) {
            int ca = j * 256 + tid;
            int row = ca >> 4, k4 = ca & 15;
            cpa16(sa + (row * GAPI + (k4 << 2)) * 4,
                  A + (size_t)(m0 + row) * DD + k0 + (k4 << 2));
        }
#pragma unroll
        for (int j = 0; j < 8; j++) {
            int cb = j * 256 + tid;
            int row = cb >> 5, n4 = cb & 31;
            cpa16(sb + (row * GBPI + (n4 << 2)) * 4,
                  W + (size_t)(k0 + row) * DD + n0 + (n4 << 2));
        }
        cpa_commit();
    };

    load_tile(0, 0);
    load_tile(1, 1);

    for (int kt = 0; kt < GNT; kt++) {
        if (kt + 1 < GNT) cpa_wait<1>(); else cpa_wait<0>();
        __syncthreads();
        if (kt + 2 < GNT) load_tile(kt + 2, (kt + 2) % 3);

        const int stg = kt % 3;
        const float* as = sh + stg * G_STG;
        const float* bs = as + G_ASZ;

#pragma unroll
        for (int ks = 0; ks < GKT; ks += 8) {
            uint32_t a[2][4], b[8][2];
#pragma unroll
            for (int mi = 0; mi < 2; mi++) {
                int mr = wm + (mi << 4) + g;
                a[mi][0] = tf32u(as[(mr    ) * GAPI + ks + t    ]);
                a[mi][1] = tf32u(as[(mr + 8) * GAPI + ks + t    ]);
                a[mi][2] = tf32u(as[(mr    ) * GAPI + ks + t + 4]);
                a[mi][3] = tf32u(as[(mr + 8) * GAPI + ks + t + 4]);
            }
#pragma unroll
            for (int ni = 0; ni < 8; ni++) {
                int nc = wn + (ni << 3) + g;
                b[ni][0] = __float_as_uint(bs[(ks + t    ) * GBPI + nc]);
                b[ni][1] = __float_as_uint(bs[(ks + t + 4) * GBPI + nc]);
            }
#pragma unroll
            for (int mi = 0; mi < 2; mi++)
#pragma unroll
                for (int ni = 0; ni < 8; ni++)
                    mma_tf32(c[mi][ni], a[mi], b[ni]);
        }
    }

#pragma unroll
    for (int ni = 0; ni < 8; ni++) {
        int col = n0 + wn + (ni << 3) + (t << 1);
        float2 bv = *(const float2*)(bias + col);
#pragma unroll
        for (int mi = 0; mi < 2; mi++) {
            int row = m0 + wm + (mi << 4) + g;
            float2 v0 = make_float2(c[mi][ni][0] + bv.x, c[mi][ni][1] + bv.y);
            float2 v1 = make_float2(c[mi][ni][2] + bv.x, c[mi][ni][3] + bv.y);
            *(float2*)(C + (size_t)row       * DD + col) = v0;
            *(float2*)(C + (size_t)(row + 8) * DD + col) = v1;
        }
    }
}

// =============================================================================
// TF32 tensor-core flash attention (causal) — unchanged from round 3.
// =============================================================================
#define FPAD 68
#define VPAD 72
#define ATT_SMEM ((128*FPAD + 64*FPAD + 64*VPAD + 128*FPAD) * 4)

__global__ __launch_bounds__(128) void flash_mma_kernel(
    const float* __restrict__ Q, const float* __restrict__ K,
    const float* __restrict__ V, float* __restrict__ O)
{
    const int qt = (SS / 128 - 1) - blockIdx.x;
    const int h  = blockIdx.y;
    const int b  = blockIdx.z;
    const int tid  = threadIdx.x;
    const int warp = tid >> 5;
    const int lane = tid & 31;
    const int g    = lane >> 2;
    const int t    = lane & 3;
    const int wm   = warp << 5;

    extern __shared__ float sm[];
    float* Qs = sm;
    float* Ks = Qs + 128 * FPAD;
    float* Vs = Ks + 64 * FPAD;
    float* Ps = Vs + 64 * VPAD;

    const float* Qb = Q + ((size_t)(b * SS + qt * 128)) * DD + h * DKH;
#pragma unroll
    for (int i = 0; i < 16; i++) {
        int e = i * 128 + tid;
        int r = e >> 4;
        int c = (e & 15) << 2;
        float4 v = *(const float4*)(Qb + (size_t)r * DD + c);
        Qs[r * FPAD + c + 0] = tf32r(v.x);
        Qs[r * FPAD + c + 1] = tf32r(v.y);
        Qs[r * FPAD + c + 2] = tf32r(v.z);
        Qs[r * FPAD + c + 3] = tf32r(v.w);
    }

    float m_i[2][2], l_i[2][2], co[2][8][4];
#pragma unroll
    for (int mi = 0; mi < 2; mi++)
#pragma unroll
        for (int hh = 0; hh < 2; hh++) { m_i[mi][hh] = -INFINITY; l_i[mi][hh] = 0.f; }
#pragma unroll
    for (int mi = 0; mi < 2; mi++)
#pragma unroll
        for (int ni = 0; ni < 8; ni++)
#pragma unroll
            for (int j = 0; j < 4; j++) co[mi][ni][j] = 0.f;

    const int ktmax = 2 * qt + 1;

    for (int kt = 0; kt <= ktmax; kt++) {
        __syncthreads();

        const float* Kb = K + ((size_t)(b * SS + kt * 64)) * DD + h * DKH;
        const float* Vb = V + ((size_t)(b * SS + kt * 64)) * DD + h * DKH;
#pragma unroll
        for (int i = 0; i < 8; i++) {
            int e = i * 128 + tid;
            int r = e >> 4;
            int c = (e & 15) << 2;
            float4 kv = *(const float4*)(Kb + (size_t)r * DD + c);
            Ks[r * FPAD + c + 0] = tf32r(kv.x);
            Ks[r * FPAD + c + 1] = tf32r(kv.y);
            Ks[r * FPAD + c + 2] = tf32r(kv.z);
            Ks[r * FPAD + c + 3] = tf32r(kv.w);
            float4 vv = *(const float4*)(Vb + (size_t)r * DD + c);
            Vs[r * VPAD + c + 0] = tf32r(vv.x);
            Vs[r * VPAD + c + 1] = tf32r(vv.y);
            Vs[r * VPAD + c + 2] = tf32r(vv.z);
            Vs[r * VPAD + c + 3] = tf32r(vv.w);
        }
        __syncthreads();

        float cs[2][8][4];
#pragma unroll
        for (int mi = 0; mi < 2; mi++)
#pragma unroll
            for (int ni = 0; ni < 8; ni++)
#pragma unroll
                for (int j = 0; j < 4; j++) cs[mi][ni][j] = 0.f;

#pragma unroll
        for (int ks = 0; ks < 8; ks++) {
            uint32_t a[2][4], bf[8][2];
#pragma unroll
            for (int mi = 0; mi < 2; mi++) {
                int row = wm + (mi << 4) + g;
                a[mi][0] = __float_as_uint(Qs[(row    ) * FPAD + (ks << 3) + t    ]);
                a[mi][1] = __float_as_uint(Qs[(row + 8) * FPAD + (ks << 3) + t    ]);
                a[mi][2] = __float_as_uint(Qs[(row    ) * FPAD + (ks << 3) + t + 4]);
                a[mi][3] = __float_as_uint(Qs[(row + 8) * FPAD + (ks << 3) + t + 4]);
            }
#pragma unroll
            for (int ni = 0; ni < 8; ni++) {
                int key = (ni << 3) + g;
                bf[ni][0] = __float_as_uint(Ks[key * FPAD + (ks << 3) + t    ]);
                bf[ni][1] = __float_as_uint(Ks[key * FPAD + (ks << 3) + t + 4]);
            }
#pragma unroll
            for (int mi = 0; mi < 2; mi++)
#pragma unroll
                for (int ni = 0; ni < 8; ni++)
                    mma_tf32(cs[mi][ni], a[mi], bf[ni]);
        }

        const bool need_mask = (kt >= 2 * qt);
#pragma unroll
        for (int mi = 0; mi < 2; mi++)
#pragma unroll
            for (int ni = 0; ni < 8; ni++)
#pragma unroll
                for (int j = 0; j < 4; j++) {
                    float s = cs[mi][ni][j] * 0.125f;
                    if (need_mask) {
                        int row = qt * 128 + wm + (mi << 4) + g + ((j >> 1) << 3);
                        int col = kt * 64 + (ni << 3) + (t << 1) + (j & 1);
                        if (col > row) s = -1e9f;
                    }
                    cs[mi][ni][j] = s;
                }

        float mt[2][2];
#pragma unroll
        for (int mi = 0; mi < 2; mi++)
#pragma unroll
            for (int hh = 0; hh < 2; hh++) {
                float mx = -INFINITY;
#pragma unroll
                for (int ni = 0; ni < 8; ni++)
                    mx = fmaxf(mx, fmaxf(cs[mi][ni][2*hh], cs[mi][ni][2*hh+1]));
                mx = fmaxf(mx, __shfl_xor_sync(0xffffffffu, mx, 1));
                mx = fmaxf(mx, __shfl_xor_sync(0xffffffffu, mx, 2));
                mt[mi][hh] = mx;
            }

        float al[2][2], mn[2][2];
#pragma unroll
        for (int mi = 0; mi < 2; mi++)
#pragma unroll
            for (int hh = 0; hh < 2; hh++) {
                float m2 = fmaxf(m_i[mi][hh], mt[mi][hh]);
                al[mi][hh] = __expf(m_i[mi][hh] - m2);
                m_i[mi][hh] = m2;
                mn[mi][hh] = m2;
            }

        float rs[2][2] = {{0.f,0.f},{0.f,0.f}};
#pragma unroll
        for (int mi = 0; mi < 2; mi++)
#pragma unroll
            for (int ni = 0; ni < 8; ni++)
#pragma unroll
                for (int j = 0; j < 4; j++) {
                    int hh = j >> 1;
                    float e = __expf(cs[mi][ni][j] - mn[mi][hh]);
                    cs[mi][ni][j] = e;
                    rs[mi][hh] += e;
                }
#pragma unroll
        for (int mi = 0; mi < 2; mi++)
#pragma unroll
            for (int hh = 0; hh < 2; hh++) {
                float r = rs[mi][hh];
                r += __shfl_xor_sync(0xffffffffu, r, 1);
                r += __shfl_xor_sync(0xffffffffu, r, 2);
                l_i[mi][hh] = l_i[mi][hh] * al[mi][hh] + r;
            }
#pragma unroll
        for (int mi = 0; mi < 2; mi++)
#pragma unroll
            for (int ni = 0; ni < 8; ni++)
#pragma unroll
                for (int j = 0; j < 4; j++)
                    co[mi][ni][j] *= al[mi][j >> 1];

#pragma unroll
        for (int mi = 0; mi < 2; mi++) {
            int row = wm + (mi << 4) + g;
#pragma unroll
            for (int ni = 0; ni < 8; ni++) {
                int col = (ni << 3) + (t << 1);
                float2 p0 = make_float2(tf32r(cs[mi][ni][0]), tf32r(cs[mi][ni][1]));
                float2 p1 = make_float2(tf32r(cs[mi][ni][2]), tf32r(cs[mi][ni][3]));
                *(float2*)&Ps[(row    ) * FPAD + col] = p0;
                *(float2*)&Ps[(row + 8) * FPAD + col] = p1;
            }
        }
        __syncwarp();

#pragma unroll
        for (int ks = 0; ks < 8; ks++) {
            uint32_t a[2][4], bf[8][2];
#pragma unroll
            for (int mi = 0; mi < 2; mi++) {
                int row = wm + (mi << 4) + g;
                a[mi][0] = __float_as_uint(Ps[(row    ) * FPAD + (ks << 3) + t    ]);
                a[mi][1] = __float_as_uint(Ps[(row + 8) * FPAD + (ks << 3) + t    ]);
                a[mi][2] = __float_as_uint(Ps[(row    ) * FPAD + (ks << 3) + t + 4]);
                a[mi][3] = __float_as_uint(Ps[(row + 8) * FPAD + (ks << 3) + t + 4]);
            }
#pragma unroll
            for (int ni = 0; ni < 8; ni++) {
                bf[ni][0] = __float_as_uint(Vs[((ks << 3) + t    ) * VPAD + (ni << 3) + g]);
                bf[ni][1] = __float_as_uint(Vs[((ks << 3) + t + 4) * VPAD + (ni << 3) + g]);
            }
#pragma unroll
            for (int mi = 0; mi < 2; mi++)
#pragma unroll
                for (int ni = 0; ni < 8; ni++)
                    mma_tf32(co[mi][ni], a[mi], bf[ni]);
        }
    }

#pragma unroll
    for (int mi = 0; mi < 2; mi++)
#pragma unroll
        for (int hh = 0; hh < 2; hh++) {
            float inv = 1.f / l_i[mi][hh];
            int row = qt * 128 + wm + (mi << 4) + g + (hh << 3);
            float* ob = O + ((size_t)(b * SS + row)) * DD + h * DKH;
#pragma unroll
            for (int ni = 0; ni < 8; ni++) {
                int col = (ni << 3) + (t << 1);
                float2 v = make_float2(tf32r(co[mi][ni][2*hh]   * inv),
                                       tf32r(co[mi][ni][2*hh+1] * inv));
                *(float2*)(ob + col) = v;
            }
        }
}

// =============================================================================
// Launch
// =============================================================================
extern "C" void kernel_launch(void* const* d_in, const int* in_sizes, int n_in,
                              void* d_out, int out_size)
{
    const float* q  = (const float*)d_in[1];
    const float* k  = (const float*)d_in[2];
    const float* v  = (const float*)d_in[3];
    const float* wq = (const float*)d_in[5];
    const float* bq = (const float*)d_in[6];
    const float* wk = (const float*)d_in[7];
    const float* bk = (const float*)d_in[8];
    const float* wv = (const float*)d_in[9];
    const float* bv = (const float*)d_in[10];
    const float* wo = (const float*)d_in[11];
    const float* bo = (const float*)d_in[12];
    float* out = (float*)d_out;

    float *gq, *gk, *gv, *gao, *wwq, *wwk, *wwv, *wwo;
    cudaGetSymbolAddress((void**)&gq,  g_Q);
    cudaGetSymbolAddress((void**)&gk,  g_K);
    cudaGetSymbolAddress((void**)&gv,  g_V);
    cudaGetSymbolAddress((void**)&gao, g_AO);
    cudaGetSymbolAddress((void**)&wwq, g_Wq);
    cudaGetSymbolAddress((void**)&wwk, g_Wk);
    cudaGetSymbolAddress((void**)&wwv, g_Wv);
    cudaGetSymbolAddress((void**)&wwo, g_Wo);

    cudaFuncSetAttribute(flash_mma_kernel,
                         cudaFuncAttributeMaxDynamicSharedMemorySize, ATT_SMEM);
    cudaFuncSetAttribute(gemm_hmma,
                         cudaFuncAttributeMaxDynamicSharedMemorySize, G_SMEM);

    const int nW4 = DD * DD / 4;
    round_tf32_kernel<<<nW4 / 256, 256>>>(wq, wwq, nW4);
    round_tf32_kernel<<<nW4 / 256, 256>>>(wk, wwk, nW4);
    round_tf32_kernel<<<nW4 / 256, 256>>>(wv, wwv, nW4);
    round_tf32_kernel<<<nW4 / 256, 256>>>(wo, wwo, nW4);

    dim3 gblk(256);
    dim3 ggrid(DD / 128, MTOT / 128);   // (8, 64)

    gemm_hmma<<<ggrid, gblk, G_SMEM>>>(q,   wwq, bq, gq);
    gemm_hmma<<<ggrid, gblk, G_SMEM>>>(k,   wwk, bk, gk);
    gemm_hmma<<<ggrid, gblk, G_SMEM>>>(v,   wwv, bv, gv);

    dim3 agrid(SS / 128, HH, BB);
    flash_mma_kernel<<<agrid, dim3(128), ATT_SMEM>>>(gq, gk, gv, gao);

    gemm_hmma<<<ggrid, gblk, G_SMEM>>>(gao, wwo, bo, out);
}

// round 7
// speedup vs baseline: 1.7909x; 1.7909x over previous
#include <cuda_runtime.h>
#include <cuda_fp16.h>
#include <math.h>
#include <stdint.h>

// Problem constants
#define BB 4
#define SS 2048
#define DD 1024
#define HH 16
#define DKH 64
#define MTOT (BB*SS)          // 8192 rows

// ---------------- scratch (static device globals; no allocation) -------------
__device__ __half g_Aq[MTOT*DD];   // half-converted inputs
__device__ __half g_Ak[MTOT*DD];
__device__ __half g_Av[MTOT*DD];
__device__ __half g_Qh[MTOT*DD];   // projection outputs (half)
__device__ __half g_Kh[MTOT*DD];
__device__ __half g_Vh[MTOT*DD];
__device__ __half g_AOh[MTOT*DD];  // attention output (half)
__device__ __half g_Wq[DD*DD];     // WT[n][k] half
__device__ __half g_Wk[DD*DD];
__device__ __half g_Wv[DD*DD];
__device__ __half g_Wo[DD*DD];

// ---------------- helpers -----------------------------------------------------
__device__ __forceinline__ uint32_t pkh2(float a, float b) {
    __half2 h = __floats2half2_rn(a, b);
    return *(uint32_t*)&h;
}
__device__ __forceinline__ void cpa16(uint32_t smem, const void* gmem) {
    asm volatile("cp.async.cg.shared.global [%0], [%1], 16;" :: "r"(smem), "l"(gmem));
}
__device__ __forceinline__ void cpa_commit() {
    asm volatile("cp.async.commit_group;");
}
template<int N> __device__ __forceinline__ void cpa_wait() {
    asm volatile("cp.async.wait_group %0;" :: "n"(N));
}
__device__ __forceinline__ uint32_t smem_u32(const void* p) {
    uint32_t a;
    asm("{ .reg .u64 t; cvta.to.shared.u64 t, %1; cvt.u32.u64 %0, t; }"
        : "=r"(a) : "l"(p));
    return a;
}
__device__ __forceinline__ void mma_f16(
    float c[4], const uint32_t a[4], const uint32_t b[2])
{
    asm volatile(
        "mma.sync.aligned.m16n8k16.row.col.f32.f16.f16.f32 "
        "{%0,%1,%2,%3}, {%4,%5,%6,%7}, {%8,%9}, {%0,%1,%2,%3};"
        : "+f"(c[0]), "+f"(c[1]), "+f"(c[2]), "+f"(c[3])
        : "r"(a[0]), "r"(a[1]), "r"(a[2]), "r"(a[3]),
          "r"(b[0]), "r"(b[1]));
}
__device__ __forceinline__ void ldsm4t(
    uint32_t& r0, uint32_t& r1, uint32_t& r2, uint32_t& r3, uint32_t a)
{
    asm volatile("ldmatrix.sync.aligned.m8n8.x4.trans.shared.b16 {%0,%1,%2,%3}, [%4];"
                 : "=r"(r0), "=r"(r1), "=r"(r2), "=r"(r3) : "r"(a));
}

// ---------------- prepass kernels ---------------------------------------------
__global__ __launch_bounds__(256) void f32_to_f16_kernel(
    const float* __restrict__ in, __half* __restrict__ out, int n4)
{
    int i = blockIdx.x * blockDim.x + threadIdx.x;
    if (i < n4) {
        float4 v = ((const float4*)in)[i];
        uint2 o;
        o.x = pkh2(v.x, v.y);
        o.y = pkh2(v.z, v.w);
        ((uint2*)out)[i] = o;
    }
}

// WT[n][k] = half(W[k][n])
__global__ __launch_bounds__(256) void wt_trans_f16_kernel(
    const float* __restrict__ in, __half* __restrict__ out)
{
    __shared__ float tl[32][33];
    const int tx = threadIdx.x, ty = threadIdx.y;
    const int n0 = blockIdx.x * 32, k0 = blockIdx.y * 32;
#pragma unroll
    for (int i = 0; i < 4; i++)
        tl[ty + i * 8][tx] = in[(size_t)(k0 + ty + i * 8) * DD + n0 + tx];
    __syncthreads();
#pragma unroll
    for (int i = 0; i < 4; i++)
        out[(size_t)(n0 + ty + i * 8) * DD + k0 + tx] = __float2half(tl[tx][ty + i * 8]);
}

// =============================================================================
// FP16 HMMA GEMM: C[M,N] = A[M,K] @ WT[N,K]^T + bias.
// A, WT half (K-major). Block tile 128x128, K-tile 64 halfs, 256 threads
// (8 warps, warp tile 32x64), mma.m16n8k16, 3-stage cp.async ring
// (110.6 KB smem -> 2 CTAs/SM), one __syncthreads per K-iteration.
// Smem pitch 72 halfs (36 words): fragment lane addr = 4g+t, conflict-free.
// =============================================================================
#define HP 72
#define G_STG_H (2 * 128 * HP)            // halfs per stage (A+B)
#define G_SMEM (3 * G_STG_H * 2)          // 110592 bytes
#define GNT (DD / 64)                     // 16 K-iterations

template<bool HOUT>
__global__ __launch_bounds__(256) void gemm_f16(
    const __half* __restrict__ A, const __half* __restrict__ WT,
    const float* __restrict__ bias, void* __restrict__ Cout)
{
    extern __shared__ __half shh[];

    const int tid  = threadIdx.x;
    const int wid  = tid >> 5;
    const int lane = tid & 31;
    const int g    = lane >> 2;
    const int t    = lane & 3;
    const int wm   = (wid & 3) << 5;
    const int wn   = (wid >> 2) << 6;
    const int m0   = blockIdx.y << 7;
    const int n0   = blockIdx.x << 7;

    float c[2][8][4];
#pragma unroll
    for (int mi = 0; mi < 2; mi++)
#pragma unroll
        for (int ni = 0; ni < 8; ni++)
#pragma unroll
            for (int j = 0; j < 4; j++) c[mi][ni][j] = 0.f;

    const uint32_t shbase = smem_u32(shh);

    auto load_tile = [&](int kt, int stg) {
        const int k0 = kt << 6;
        const uint32_t sa = shbase + (stg * G_STG_H) * 2;
        const uint32_t sb = sa + 128 * HP * 2;
#pragma unroll
        for (int j = 0; j < 4; j++) {          // A: 128 rows x 8 chunks
            int ca = j * 256 + tid;
            int row = ca >> 3, k8 = ca & 7;
            cpa16(sa + (row * HP + (k8 << 3)) * 2,
                  A + (size_t)(m0 + row) * DD + k0 + (k8 << 3));
        }
#pragma unroll
        for (int j = 0; j < 4; j++) {          // B: 128 n-rows x 8 chunks
            int cb = j * 256 + tid;
            int row = cb >> 3, k8 = cb & 7;
            cpa16(sb + (row * HP + (k8 << 3)) * 2,
                  WT + (size_t)(n0 + row) * DD + k0 + (k8 << 3));
        }
        cpa_commit();
    };

    load_tile(0, 0);
    load_tile(1, 1);

    for (int kt = 0; kt < GNT; kt++) {
        if (kt + 1 < GNT) cpa_wait<1>(); else cpa_wait<0>();
        __syncthreads();
        if (kt + 2 < GNT) load_tile(kt + 2, (kt + 2) % 3);

        const int stg = kt % 3;
        const __half* as = shh + stg * G_STG_H;
        const __half* bs = as + 128 * HP;

#pragma unroll
        for (int ks = 0; ks < 4; ks++) {       // k16 steps
            uint32_t a[2][4], b[8][2];
#pragma unroll
            for (int mi = 0; mi < 2; mi++) {
                int mr = wm + (mi << 4) + g;
                a[mi][0] = *(const uint32_t*)&as[(mr    ) * HP + (ks << 4) + (t << 1)];
                a[mi][1] = *(const uint32_t*)&as[(mr + 8) * HP + (ks << 4) + (t << 1)];
                a[mi][2] = *(const uint32_t*)&as[(mr    ) * HP + (ks << 4) + 8 + (t << 1)];
                a[mi][3] = *(const uint32_t*)&as[(mr + 8) * HP + (ks << 4) + 8 + (t << 1)];
            }
#pragma unroll
            for (int ni = 0; ni < 8; ni++) {
                int nc = wn + (ni << 3) + g;
                b[ni][0] = *(const uint32_t*)&bs[nc * HP + (ks << 4) + (t << 1)];
                b[ni][1] = *(const uint32_t*)&bs[nc * HP + (ks << 4) + 8 + (t << 1)];
            }
#pragma unroll
            for (int mi = 0; mi < 2; mi++)
#pragma unroll
                for (int ni = 0; ni < 8; ni++)
                    mma_f16(c[mi][ni], a[mi], b[ni]);
        }
    }

    // ---- epilogue: bias + store ----
#pragma unroll
    for (int ni = 0; ni < 8; ni++) {
        int col = n0 + wn + (ni << 3) + (t << 1);
        float2 bv = *(const float2*)(bias + col);
#pragma unroll
        for (int mi = 0; mi < 2; mi++) {
            int row = m0 + wm + (mi << 4) + g;
            if (HOUT) {
                __half* C = (__half*)Cout;
                *(uint32_t*)(C + (size_t)row       * DD + col) =
                    pkh2(c[mi][ni][0] + bv.x, c[mi][ni][1] + bv.y);
                *(uint32_t*)(C + (size_t)(row + 8) * DD + col) =
                    pkh2(c[mi][ni][2] + bv.x, c[mi][ni][3] + bv.y);
            } else {
                float* C = (float*)Cout;
                float2 v0 = make_float2(c[mi][ni][0] + bv.x, c[mi][ni][1] + bv.y);
                float2 v1 = make_float2(c[mi][ni][2] + bv.x, c[mi][ni][3] + bv.y);
                *(float2*)(C + (size_t)row       * DD + col) = v0;
                *(float2*)(C + (size_t)(row + 8) * DD + col) = v1;
            }
        }
    }
}

// =============================================================================
// FP16 tensor-core flash attention (causal). Same structure as round 3 but all
// tiles are half, mma.m16n8k16. V operand of P@V via ldmatrix.x4.trans.
// Smem: Qs[128][72] + Ks[64][72] + Vs[64][72] + Ps[128][72] halfs = 55296 B.
// =============================================================================
#define ATT_SMEM ((128*HP + 64*HP + 64*HP + 128*HP) * 2)

__global__ __launch_bounds__(128) void flash_f16_kernel(
    const __half* __restrict__ Q, const __half* __restrict__ K,
    const __half* __restrict__ V, __half* __restrict__ O)
{
    const int qt = (SS / 128 - 1) - blockIdx.x;   // heavy blocks first
    const int h  = blockIdx.y;
    const int b  = blockIdx.z;
    const int tid  = threadIdx.x;
    const int warp = tid >> 5;
    const int lane = tid & 31;
    const int g    = lane >> 2;
    const int t    = lane & 3;
    const int wm   = warp << 5;

    extern __shared__ __half smh[];
    __half* Qs = smh;                 // [128][HP]
    __half* Ks = Qs + 128 * HP;       // [64][HP]
    __half* Vs = Ks + 64 * HP;        // [64][HP]
    __half* Ps = Vs + 64 * HP;        // [128][HP]

    // ldmatrix per-thread address parts for V
    const int vrow = ((lane >> 3) & 1) * 8 + (lane & 7);
    const int vcol = (lane >> 4) * 8;
    const uint32_t vbase = smem_u32(Vs);

    // ---- load Q tile (128 x 64 halfs) ----
    const __half* Qb = Q + ((size_t)(b * SS + qt * 128)) * DD + h * DKH;
#pragma unroll
    for (int i = 0; i < 8; i++) {
        int e = i * 128 + tid;        // 16-byte chunk index
        int r = e >> 3;
        int c8 = e & 7;
        *(uint4*)&Qs[r * HP + (c8 << 3)] = *(const uint4*)(Qb + (size_t)r * DD + (c8 << 3));
    }

    float m_i[2][2], l_i[2][2], co[2][8][4];
#pragma unroll
    for (int mi = 0; mi < 2; mi++)
#pragma unroll
        for (int hh = 0; hh < 2; hh++) { m_i[mi][hh] = -INFINITY; l_i[mi][hh] = 0.f; }
#pragma unroll
    for (int mi = 0; mi < 2; mi++)
#pragma unroll
        for (int ni = 0; ni < 8; ni++)
#pragma unroll
            for (int j = 0; j < 4; j++) co[mi][ni][j] = 0.f;

    const int ktmax = 2 * qt + 1;

    for (int kt = 0; kt <= ktmax; kt++) {
        __syncthreads();

        const __half* Kb = K + ((size_t)(b * SS + kt * 64)) * DD + h * DKH;
        const __half* Vb = V + ((size_t)(b * SS + kt * 64)) * DD + h * DKH;
#pragma unroll
        for (int i = 0; i < 4; i++) {
            int e = i * 128 + tid;
            int r = e >> 3;
            int c8 = e & 7;
            *(uint4*)&Ks[r * HP + (c8 << 3)] = *(const uint4*)(Kb + (size_t)r * DD + (c8 << 3));
            *(uint4*)&Vs[r * HP + (c8 << 3)] = *(const uint4*)(Vb + (size_t)r * DD + (c8 << 3));
        }
        __syncthreads();

        // ---- S = Q K^T ----
        float cs[2][8][4];
#pragma unroll
        for (int mi = 0; mi < 2; mi++)
#pragma unroll
            for (int ni = 0; ni < 8; ni++)
#pragma unroll
                for (int j = 0; j < 4; j++) cs[mi][ni][j] = 0.f;

#pragma unroll
        for (int ks = 0; ks < 4; ks++) {
            uint32_t a[2][4], bf[8][2];
#pragma unroll
            for (int mi = 0; mi < 2; mi++) {
                int row = wm + (mi << 4) + g;
                a[mi][0] = *(const uint32_t*)&Qs[(row    ) * HP + (ks << 4) + (t << 1)];
                a[mi][1] = *(const uint32_t*)&Qs[(row + 8) * HP + (ks << 4) + (t << 1)];
                a[mi][2] = *(const uint32_t*)&Qs[(row    ) * HP + (ks << 4) + 8 + (t << 1)];
                a[mi][3] = *(const uint32_t*)&Qs[(row + 8) * HP + (ks << 4) + 8 + (t << 1)];
            }
#pragma unroll
            for (int ni = 0; ni < 8; ni++) {
                int key = (ni << 3) + g;
                bf[ni][0] = *(const uint32_t*)&Ks[key * HP + (ks << 4) + (t << 1)];
                bf[ni][1] = *(const uint32_t*)&Ks[key * HP + (ks << 4) + 8 + (t << 1)];
            }
#pragma unroll
            for (int mi = 0; mi < 2; mi++)
#pragma unroll
                for (int ni = 0; ni < 8; ni++)
                    mma_f16(cs[mi][ni], a[mi], bf[ni]);
        }

        // ---- scale + causal mask ----
        const bool need_mask = (kt >= 2 * qt);
#pragma unroll
        for (int mi = 0; mi < 2; mi++)
#pragma unroll
            for (int ni = 0; ni < 8; ni++)
#pragma unroll
                for (int j = 0; j < 4; j++) {
                    float s = cs[mi][ni][j] * 0.125f;
                    if (need_mask) {
                        int row = qt * 128 + wm + (mi << 4) + g + ((j >> 1) << 3);
                        int col = kt * 64 + (ni << 3) + (t << 1) + (j & 1);
                        if (col > row) s = -1e9f;
                    }
                    cs[mi][ni][j] = s;
                }

        // ---- online softmax ----
        float mt[2][2];
#pragma unroll
        for (int mi = 0; mi < 2; mi++)
#pragma unroll
            for (int hh = 0; hh < 2; hh++) {
                float mx = -INFINITY;
#pragma unroll
                for (int ni = 0; ni < 8; ni++)
                    mx = fmaxf(mx, fmaxf(cs[mi][ni][2*hh], cs[mi][ni][2*hh+1]));
                mx = fmaxf(mx, __shfl_xor_sync(0xffffffffu, mx, 1));
                mx = fmaxf(mx, __shfl_xor_sync(0xffffffffu, mx, 2));
                mt[mi][hh] = mx;
            }

        float al[2][2], mn[2][2];
#pragma unroll
        for (int mi = 0; mi < 2; mi++)
#pragma unroll
            for (int hh = 0; hh < 2; hh++) {
                float m2 = fmaxf(m_i[mi][hh], mt[mi][hh]);
                al[mi][hh] = __expf(m_i[mi][hh] - m2);
                m_i[mi][hh] = m2;
                mn[mi][hh] = m2;
            }

        float rs[2][2] = {{0.f,0.f},{0.f,0.f}};
#pragma unroll
        for (int mi = 0; mi < 2; mi++)
#pragma unroll
            for (int ni = 0; ni < 8; ni++)
#pragma unroll
                for (int j = 0; j < 4; j++) {
                    int hh = j >> 1;
                    float e = __expf(cs[mi][ni][j] - mn[mi][hh]);
                    cs[mi][ni][j] = e;
                    rs[mi][hh] += e;
                }
#pragma unroll
        for (int mi = 0; mi < 2; mi++)
#pragma unroll
            for (int hh = 0; hh < 2; hh++) {
                float r = rs[mi][hh];
                r += __shfl_xor_sync(0xffffffffu, r, 1);
                r += __shfl_xor_sync(0xffffffffu, r, 2);
                l_i[mi][hh] = l_i[mi][hh] * al[mi][hh] + r;
            }
#pragma unroll
        for (int mi = 0; mi < 2; mi++)
#pragma unroll
            for (int ni = 0; ni < 8; ni++)
#pragma unroll
                for (int j = 0; j < 4; j++)
                    co[mi][ni][j] *= al[mi][j >> 1];

        // ---- store P (half) to warp-private rows ----
#pragma unroll
        for (int mi = 0; mi < 2; mi++) {
            int row = wm + (mi << 4) + g;
#pragma unroll
            for (int ni = 0; ni < 8; ni++) {
                int col = (ni << 3) + (t << 1);
                *(uint32_t*)&Ps[(row    ) * HP + col] = pkh2(cs[mi][ni][0], cs[mi][ni][1]);
                *(uint32_t*)&Ps[(row + 8) * HP + col] = pkh2(cs[mi][ni][2], cs[mi][ni][3]);
            }
        }
        __syncwarp();

        // ---- O += P @ V  (V via ldmatrix.x4.trans) ----
#pragma unroll
        for (int ks = 0; ks < 4; ks++) {
            uint32_t a[2][4], bf[8][2];
#pragma unroll
            for (int mi = 0; mi < 2; mi++) {
                int row = wm + (mi << 4) + g;
                a[mi][0] = *(const uint32_t*)&Ps[(row    ) * HP + (ks << 4) + (t << 1)];
                a[mi][1] = *(const uint32_t*)&Ps[(row + 8) * HP + (ks << 4) + (t << 1)];
                a[mi][2] = *(const uint32_t*)&Ps[(row    ) * HP + (ks << 4) + 8 + (t << 1)];
                a[mi][3] = *(const uint32_t*)&Ps[(row + 8) * HP + (ks << 4) + 8 + (t << 1)];
            }
#pragma unroll
            for (int nn = 0; nn < 4; nn++) {
                uint32_t addr = vbase + (((ks << 4) + vrow) * HP + (nn << 4) + vcol) * 2;
                ldsm4t(bf[2*nn][0], bf[2*nn][1], bf[2*nn+1][0], bf[2*nn+1][1], addr);
            }
#pragma unroll
            for (int mi = 0; mi < 2; mi++)
#pragma unroll
                for (int ni = 0; ni < 8; ni++)
                    mma_f16(co[mi][ni], a[mi], bf[ni]);
        }
    }

    // ---- epilogue: normalize, store half ----
#pragma unroll
    for (int mi = 0; mi < 2; mi++)
#pragma unroll
        for (int hh = 0; hh < 2; hh++) {
            float inv = 1.f / l_i[mi][hh];
            int row = qt * 128 + wm + (mi << 4) + g + (hh << 3);
            __half* ob = O + ((size_t)(b * SS + row)) * DD + h * DKH;
#pragma unroll
            for (int ni = 0; ni < 8; ni++) {
                int col = (ni << 3) + (t << 1);
                *(uint32_t*)(ob + col) = pkh2(co[mi][ni][2*hh] * inv,
                                              co[mi][ni][2*hh+1] * inv);
            }
        }
}

// =============================================================================
// Launch
// =============================================================================
extern "C" void kernel_launch(void* const* d_in, const int* in_sizes, int n_in,
                              void* d_out, int out_size)
{
    const float* q  = (const float*)d_in[1];
    const float* k  = (const float*)d_in[2];
    const float* v  = (const float*)d_in[3];
    const float* wq = (const float*)d_in[5];
    const float* bq = (const float*)d_in[6];
    const float* wk = (const float*)d_in[7];
    const float* bk = (const float*)d_in[8];
    const float* wv = (const float*)d_in[9];
    const float* bv = (const float*)d_in[10];
    const float* wo = (const float*)d_in[11];
    const float* bo = (const float*)d_in[12];
    float* out = (float*)d_out;

    __half *aq, *ak, *av, *qh, *kh, *vh, *aoh, *wtq, *wtk, *wtv, *wto;
    cudaGetSymbolAddress((void**)&aq,  g_Aq);
    cudaGetSymbolAddress((void**)&ak,  g_Ak);
    cudaGetSymbolAddress((void**)&av,  g_Av);
    cudaGetSymbolAddress((void**)&qh,  g_Qh);
    cudaGetSymbolAddress((void**)&kh,  g_Kh);
    cudaGetSymbolAddress((void**)&vh,  g_Vh);
    cudaGetSymbolAddress((void**)&aoh, g_AOh);
    cudaGetSymbolAddress((void**)&wtq, g_Wq);
    cudaGetSymbolAddress((void**)&wtk, g_Wk);
    cudaGetSymbolAddress((void**)&wtv, g_Wv);
    cudaGetSymbolAddress((void**)&wto, g_Wo);

    cudaFuncSetAttribute(flash_f16_kernel,
                         cudaFuncAttributeMaxDynamicSharedMemorySize, ATT_SMEM);
    cudaFuncSetAttribute(gemm_f16<true>,
                         cudaFuncAttributeMaxDynamicSharedMemorySize, G_SMEM);
    cudaFuncSetAttribute(gemm_f16<false>,
                         cudaFuncAttributeMaxDynamicSharedMemorySize, G_SMEM);

    // ---- prepass: convert activations to half; convert+transpose weights ----
    const int nA4 = MTOT * DD / 4;
    f32_to_f16_kernel<<<nA4 / 256, 256>>>(q, aq, nA4);
    f32_to_f16_kernel<<<nA4 / 256, 256>>>(k, ak, nA4);
    f32_to_f16_kernel<<<nA4 / 256, 256>>>(v, av, nA4);
    dim3 tb(32, 8), tg(DD / 32, DD / 32);
    wt_trans_f16_kernel<<<tg, tb>>>(wq, wtq);
    wt_trans_f16_kernel<<<tg, tb>>>(wk, wtk);
    wt_trans_f16_kernel<<<tg, tb>>>(wv, wtv);
    wt_trans_f16_kernel<<<tg, tb>>>(wo, wto);

    // ---- projections ----
    dim3 gblk(256);
    dim3 ggrid(DD / 128, MTOT / 128);   // (8, 64)
    gemm_f16<true><<<ggrid, gblk, G_SMEM>>>(aq, wtq, bq, qh);
    gemm_f16<true><<<ggrid, gblk, G_SMEM>>>(ak, wtk, bk, kh);
    gemm_f16<true><<<ggrid, gblk, G_SMEM>>>(av, wtv, bv, vh);

    // ---- attention ----
    dim3 agrid(SS / 128, HH, BB);       // (16, 16, 4)
    flash_f16_kernel<<<agrid, dim3(128), ATT_SMEM>>>(qh, kh, vh, aoh);

    // ---- output projection (fp32 out) ----
    gemm_f16<false><<<ggrid, gblk, G_SMEM>>>(aoh, wto, bo, (void*)out);
}

// round 8
// speedup vs baseline: 1.9994x; 1.1164x over previous
#include <cuda_runtime.h>
#include <cuda_fp16.h>
#include <math.h>
#include <stdint.h>

// Problem constants
#define BB 4
#define SS 2048
#define DD 1024
#define HH 16
#define DKH 64
#define MTOT (BB*SS)          // 8192 rows

// ---------------- scratch (static device globals; no allocation) -------------
__device__ __half g_Aq[MTOT*DD];   // half-converted inputs
__device__ __half g_Ak[MTOT*DD];
__device__ __half g_Av[MTOT*DD];
__device__ __half g_Qh[MTOT*DD];   // projection outputs (half)
__device__ __half g_Kh[MTOT*DD];
__device__ __half g_Vh[MTOT*DD];
__device__ __half g_AOh[MTOT*DD];  // attention output (half)
__device__ __half g_Wq[DD*DD];     // WT[n][k] half
__device__ __half g_Wk[DD*DD];
__device__ __half g_Wv[DD*DD];
__device__ __half g_Wo[DD*DD];

// ---------------- helpers -----------------------------------------------------
__device__ __forceinline__ uint32_t pkh2(float a, float b) {
    __half2 h = __floats2half2_rn(a, b);
    return *(uint32_t*)&h;
}
__device__ __forceinline__ void cpa16(uint32_t smem, const void* gmem) {
    asm volatile("cp.async.cg.shared.global [%0], [%1], 16;" :: "r"(smem), "l"(gmem));
}
__device__ __forceinline__ void cpa_commit() {
    asm volatile("cp.async.commit_group;");
}
template<int N> __device__ __forceinline__ void cpa_wait() {
    asm volatile("cp.async.wait_group %0;" :: "n"(N));
}
__device__ __forceinline__ uint32_t smem_u32(const void* p) {
    uint32_t a;
    asm("{ .reg .u64 t; cvta.to.shared.u64 t, %1; cvt.u32.u64 %0, t; }"
        : "=r"(a) : "l"(p));
    return a;
}
__device__ __forceinline__ void mma_f16(
    float c[4], const uint32_t a[4], const uint32_t b[2])
{
    asm volatile(
        "mma.sync.aligned.m16n8k16.row.col.f32.f16.f16.f32 "
        "{%0,%1,%2,%3}, {%4,%5,%6,%7}, {%8,%9}, {%0,%1,%2,%3};"
        : "+f"(c[0]), "+f"(c[1]), "+f"(c[2]), "+f"(c[3])
        : "r"(a[0]), "r"(a[1]), "r"(a[2]), "r"(a[3]),
          "r"(b[0]), "r"(b[1]));
}
__device__ __forceinline__ void ldsm4t(
    uint32_t& r0, uint32_t& r1, uint32_t& r2, uint32_t& r3, uint32_t a)
{
    asm volatile("ldmatrix.sync.aligned.m8n8.x4.trans.shared.b16 {%0,%1,%2,%3}, [%4];"
                 : "=r"(r0), "=r"(r1), "=r"(r2), "=r"(r3) : "r"(a));
}

// ---------------- prepass kernels (merged) ------------------------------------
// grid.y selects which activation to convert
__global__ __launch_bounds__(256) void act_conv_kernel(
    const float* __restrict__ q, const float* __restrict__ k,
    const float* __restrict__ v,
    __half* __restrict__ oq, __half* __restrict__ ok, __half* __restrict__ ov)
{
    const int which = blockIdx.y;
    const float* in = (which == 0) ? q : (which == 1) ? k : v;
    __half* out     = (which == 0) ? oq : (which == 1) ? ok : ov;
    int i = blockIdx.x * blockDim.x + threadIdx.x;
    float4 vv = ((const float4*)in)[i];
    uint2 o;
    o.x = pkh2(vv.x, vv.y);
    o.y = pkh2(vv.z, vv.w);
    ((uint2*)out)[i] = o;
}

// WT[n][k] = half(W[k][n]); grid.z selects which weight
__global__ __launch_bounds__(256) void wt_trans_kernel(
    const float* __restrict__ wq, const float* __restrict__ wk,
    const float* __restrict__ wv, const float* __restrict__ wo,
    __half* __restrict__ oq, __half* __restrict__ ok,
    __half* __restrict__ ov, __half* __restrict__ oo)
{
    const int which = blockIdx.z;
    const float* in = (which == 0) ? wq : (which == 1) ? wk : (which == 2) ? wv : wo;
    __half* out     = (which == 0) ? oq : (which == 1) ? ok : (which == 2) ? ov : oo;

    __shared__ float tl[32][33];
    const int tx = threadIdx.x, ty = threadIdx.y;
    const int n0 = blockIdx.x * 32, k0 = blockIdx.y * 32;
#pragma unroll
    for (int i = 0; i < 4; i++)
        tl[ty + i * 8][tx] = in[(size_t)(k0 + ty + i * 8) * DD + n0 + tx];
    __syncthreads();
#pragma unroll
    for (int i = 0; i < 4; i++)
        out[(size_t)(n0 + ty + i * 8) * DD + k0 + tx] = __float2half(tl[tx][ty + i * 8]);
}

// =============================================================================
// FP16 HMMA GEMM (fused QKV variant): C = A @ WT^T + bias.
// blockIdx.z selects (A, WT, bias, C). Block tile 128x128, K-tile 64 halfs,
// 256 threads (8 warps, 32x64 warp tile), mma.m16n8k16, 3-stage cp.async
// ring (110.6 KB smem -> 2 CTAs/SM), one __syncthreads per K-iteration.
// =============================================================================
#define HP 72
#define G_STG_H (2 * 128 * HP)
#define G_SMEM (3 * G_STG_H * 2)          // 110592 bytes
#define GNT (DD / 64)                     // 16 K-iterations

__global__ __launch_bounds__(256) void gemm_qkv_f16(
    const __half* __restrict__ A0, const __half* __restrict__ A1,
    const __half* __restrict__ A2,
    const __half* __restrict__ W0, const __half* __restrict__ W1,
    const __half* __restrict__ W2,
    const float* __restrict__ b0, const float* __restrict__ b1,
    const float* __restrict__ b2,
    __half* __restrict__ C0, __half* __restrict__ C1, __half* __restrict__ C2)
{
    extern __shared__ __half shh[];

    const int z = blockIdx.z;
    const __half* A  = (z == 0) ? A0 : (z == 1) ? A1 : A2;
    const __half* WT = (z == 0) ? W0 : (z == 1) ? W1 : W2;
    const float* bias = (z == 0) ? b0 : (z == 1) ? b1 : b2;
    __half* C        = (z == 0) ? C0 : (z == 1) ? C1 : C2;

    const int tid  = threadIdx.x;
    const int wid  = tid >> 5;
    const int lane = tid & 31;
    const int g    = lane >> 2;
    const int t    = lane & 3;
    const int wm   = (wid & 3) << 5;
    const int wn   = (wid >> 2) << 6;
    const int m0   = blockIdx.y << 7;
    const int n0   = blockIdx.x << 7;

    float c[2][8][4];
#pragma unroll
    for (int mi = 0; mi < 2; mi++)
#pragma unroll
        for (int ni = 0; ni < 8; ni++)
#pragma unroll
            for (int j = 0; j < 4; j++) c[mi][ni][j] = 0.f;

    const uint32_t shbase = smem_u32(shh);

    auto load_tile = [&](int kt, int stg) {
        const int k0 = kt << 6;
        const uint32_t sa = shbase + (stg * G_STG_H) * 2;
        const uint32_t sb = sa + 128 * HP * 2;
#pragma unroll
        for (int j = 0; j < 4; j++) {
            int ca = j * 256 + tid;
            int row = ca >> 3, k8 = ca & 7;
            cpa16(sa + (row * HP + (k8 << 3)) * 2,
                  A + (size_t)(m0 + row) * DD + k0 + (k8 << 3));
        }
#pragma unroll
        for (int j = 0; j < 4; j++) {
            int cb = j * 256 + tid;
            int row = cb >> 3, k8 = cb & 7;
            cpa16(sb + (row * HP + (k8 << 3)) * 2,
                  WT + (size_t)(n0 + row) * DD + k0 + (k8 << 3));
        }
        cpa_commit();
    };

    load_tile(0, 0);
    load_tile(1, 1);

    for (int kt = 0; kt < GNT; kt++) {
        if (kt + 1 < GNT) cpa_wait<1>(); else cpa_wait<0>();
        __syncthreads();
        if (kt + 2 < GNT) load_tile(kt + 2, (kt + 2) % 3);

        const int stg = kt % 3;
        const __half* as = shh + stg * G_STG_H;
        const __half* bs = as + 128 * HP;

#pragma unroll
        for (int ks = 0; ks < 4; ks++) {
            uint32_t a[2][4], b[8][2];
#pragma unroll
            for (int mi = 0; mi < 2; mi++) {
                int mr = wm + (mi << 4) + g;
                a[mi][0] = *(const uint32_t*)&as[(mr    ) * HP + (ks << 4) + (t << 1)];
                a[mi][1] = *(const uint32_t*)&as[(mr + 8) * HP + (ks << 4) + (t << 1)];
                a[mi][2] = *(const uint32_t*)&as[(mr    ) * HP + (ks << 4) + 8 + (t << 1)];
                a[mi][3] = *(const uint32_t*)&as[(mr + 8) * HP + (ks << 4) + 8 + (t << 1)];
            }
#pragma unroll
            for (int ni = 0; ni < 8; ni++) {
                int nc = wn + (ni << 3) + g;
                b[ni][0] = *(const uint32_t*)&bs[nc * HP + (ks << 4) + (t << 1)];
                b[ni][1] = *(const uint32_t*)&bs[nc * HP + (ks << 4) + 8 + (t << 1)];
            }
#pragma unroll
            for (int mi = 0; mi < 2; mi++)
#pragma unroll
                for (int ni = 0; ni < 8; ni++)
                    mma_f16(c[mi][ni], a[mi], b[ni]);
        }
    }

#pragma unroll
    for (int ni = 0; ni < 8; ni++) {
        int col = n0 + wn + (ni << 3) + (t << 1);
        float2 bv = *(const float2*)(bias + col);
#pragma unroll
        for (int mi = 0; mi < 2; mi++) {
            int row = m0 + wm + (mi << 4) + g;
            *(uint32_t*)(C + (size_t)row       * DD + col) =
                pkh2(c[mi][ni][0] + bv.x, c[mi][ni][1] + bv.y);
            *(uint32_t*)(C + (size_t)(row + 8) * DD + col) =
                pkh2(c[mi][ni][2] + bv.x, c[mi][ni][3] + bv.y);
        }
    }
}

// Single GEMM (output projection, fp32 out) — same core.
__global__ __launch_bounds__(256) void gemm_o_f16(
    const __half* __restrict__ A, const __half* __restrict__ WT,
    const float* __restrict__ bias, float* __restrict__ C)
{
    extern __shared__ __half shh[];

    const int tid  = threadIdx.x;
    const int wid  = tid >> 5;
    const int lane = tid & 31;
    const int g    = lane >> 2;
    const int t    = lane & 3;
    const int wm   = (wid & 3) << 5;
    const int wn   = (wid >> 2) << 6;
    const int m0   = blockIdx.y << 7;
    const int n0   = blockIdx.x << 7;

    float c[2][8][4];
#pragma unroll
    for (int mi = 0; mi < 2; mi++)
#pragma unroll
        for (int ni = 0; ni < 8; ni++)
#pragma unroll
            for (int j = 0; j < 4; j++) c[mi][ni][j] = 0.f;

    const uint32_t shbase = smem_u32(shh);

    auto load_tile = [&](int kt, int stg) {
        const int k0 = kt << 6;
        const uint32_t sa = shbase + (stg * G_STG_H) * 2;
        const uint32_t sb = sa + 128 * HP * 2;
#pragma unroll
        for (int j = 0; j < 4; j++) {
            int ca = j * 256 + tid;
            int row = ca >> 3, k8 = ca & 7;
            cpa16(sa + (row * HP + (k8 << 3)) * 2,
                  A + (size_t)(m0 + row) * DD + k0 + (k8 << 3));
        }
#pragma unroll
        for (int j = 0; j < 4; j++) {
            int cb = j * 256 + tid;
            int row = cb >> 3, k8 = cb & 7;
            cpa16(sb + (row * HP + (k8 << 3)) * 2,
                  WT + (size_t)(n0 + row) * DD + k0 + (k8 << 3));
        }
        cpa_commit();
    };

    load_tile(0, 0);
    load_tile(1, 1);

    for (int kt = 0; kt < GNT; kt++) {
        if (kt + 1 < GNT) cpa_wait<1>(); else cpa_wait<0>();
        __syncthreads();
        if (kt + 2 < GNT) load_tile(kt + 2, (kt + 2) % 3);

        const int stg = kt % 3;
        const __half* as = shh + stg * G_STG_H;
        const __half* bs = as + 128 * HP;

#pragma unroll
        for (int ks = 0; ks < 4; ks++) {
            uint32_t a[2][4], b[8][2];
#pragma unroll
            for (int mi = 0; mi < 2; mi++) {
                int mr = wm + (mi << 4) + g;
                a[mi][0] = *(const uint32_t*)&as[(mr    ) * HP + (ks << 4) + (t << 1)];
                a[mi][1] = *(const uint32_t*)&as[(mr + 8) * HP + (ks << 4) + (t << 1)];
                a[mi][2] = *(const uint32_t*)&as[(mr    ) * HP + (ks << 4) + 8 + (t << 1)];
                a[mi][3] = *(const uint32_t*)&as[(mr + 8) * HP + (ks << 4) + 8 + (t << 1)];
            }
#pragma unroll
            for (int ni = 0; ni < 8; ni++) {
                int nc = wn + (ni << 3) + g;
                b[ni][0] = *(const uint32_t*)&bs[nc * HP + (ks << 4) + (t << 1)];
                b[ni][1] = *(const uint32_t*)&bs[nc * HP + (ks << 4) + 8 + (t << 1)];
            }
#pragma unroll
            for (int mi = 0; mi < 2; mi++)
#pragma unroll
                for (int ni = 0; ni < 8; ni++)
                    mma_f16(c[mi][ni], a[mi], b[ni]);
        }
    }

#pragma unroll
    for (int ni = 0; ni < 8; ni++) {
        int col = n0 + wn + (ni << 3) + (t << 1);
        float2 bv = *(const float2*)(bias + col);
#pragma unroll
        for (int mi = 0; mi < 2; mi++) {
            int row = m0 + wm + (mi << 4) + g;
            float2 v0 = make_float2(c[mi][ni][0] + bv.x, c[mi][ni][1] + bv.y);
            float2 v1 = make_float2(c[mi][ni][2] + bv.x, c[mi][ni][3] + bv.y);
            *(float2*)(C + (size_t)row       * DD + col) = v0;
            *(float2*)(C + (size_t)(row + 8) * DD + col) = v1;
        }
    }
}

// =============================================================================
// FP16 flash attention (causal), cp.async double-buffered K/V.
// Smem: Qs[128][72] + Ks[2][64][72] + Vs[2][64][72] + Ps[128][72] halfs
//     = 73728 B -> 3 CTAs/SM.
// =============================================================================
#define ATT_SMEM ((128*HP + 2*64*HP + 2*64*HP + 128*HP) * 2)

__global__ __launch_bounds__(128) void flash_f16_kernel(
    const __half* __restrict__ Q, const __half* __restrict__ K,
    const __half* __restrict__ V, __half* __restrict__ O)
{
    const int qt = (SS / 128 - 1) - blockIdx.x;   // heavy blocks first
    const int h  = blockIdx.y;
    const int b  = blockIdx.z;
    const int tid  = threadIdx.x;
    const int warp = tid >> 5;
    const int lane = tid & 31;
    const int g    = lane >> 2;
    const int t    = lane & 3;
    const int wm   = warp << 5;

    extern __shared__ __half smh[];
    __half* Qs = smh;                    // [128][HP]
    __half* Ks = Qs + 128 * HP;          // [2][64][HP]
    __half* Vs = Ks + 2 * 64 * HP;       // [2][64][HP]
    __half* Ps = Vs + 2 * 64 * HP;       // [128][HP]

    const uint32_t ksbase = smem_u32(Ks);
    const uint32_t vsbase = smem_u32(Vs);

    const int vrow = ((lane >> 3) & 1) * 8 + (lane & 7);
    const int vcol = (lane >> 4) * 8;

    const __half* Kh0 = K + ((size_t)(b * SS)) * DD + h * DKH;
    const __half* Vh0 = V + ((size_t)(b * SS)) * DD + h * DKH;

    auto load_kv = [&](int kt, int buf) {
        const __half* Kb = Kh0 + (size_t)(kt * 64) * DD;
        const __half* Vb = Vh0 + (size_t)(kt * 64) * DD;
        const uint32_t kb = ksbase + buf * 64 * HP * 2;
        const uint32_t vb = vsbase + buf * 64 * HP * 2;
#pragma unroll
        for (int i = 0; i < 4; i++) {
            int e = i * 128 + tid;
            int r = e >> 3;
            int c8 = e & 7;
            cpa16(kb + (r * HP + (c8 << 3)) * 2, Kb + (size_t)r * DD + (c8 << 3));
            cpa16(vb + (r * HP + (c8 << 3)) * 2, Vb + (size_t)r * DD + (c8 << 3));
        }
        cpa_commit();
    };

    // ---- load Q tile ----
    const __half* Qb = Q + ((size_t)(b * SS + qt * 128)) * DD + h * DKH;
#pragma unroll
    for (int i = 0; i < 8; i++) {
        int e = i * 128 + tid;
        int r = e >> 3;
        int c8 = e & 7;
        *(uint4*)&Qs[r * HP + (c8 << 3)] = *(const uint4*)(Qb + (size_t)r * DD + (c8 << 3));
    }

    load_kv(0, 0);

    float m_i[2][2], l_i[2][2], co[2][8][4];
#pragma unroll
    for (int mi = 0; mi < 2; mi++)
#pragma unroll
        for (int hh = 0; hh < 2; hh++) { m_i[mi][hh] = -INFINITY; l_i[mi][hh] = 0.f; }
#pragma unroll
    for (int mi = 0; mi < 2; mi++)
#pragma unroll
        for (int ni = 0; ni < 8; ni++)
#pragma unroll
            for (int j = 0; j < 4; j++) co[mi][ni][j] = 0.f;

    const int ktmax = 2 * qt + 1;

    for (int kt = 0; kt <= ktmax; kt++) {
        __syncthreads();   // buffer (kt+1)&1 reads from iter kt-1 done; Qs stores (iter 0)
        if (kt < ktmax) {
            load_kv(kt + 1, (kt + 1) & 1);
            cpa_wait<1>();
        } else {
            cpa_wait<0>();
        }
        __syncthreads();   // tile kt visible to all threads

        const __half* Kst = Ks + (kt & 1) * 64 * HP;
        const uint32_t vtile = vsbase + (kt & 1) * 64 * HP * 2;

        // ---- S = Q K^T ----
        float cs[2][8][4];
#pragma unroll
        for (int mi = 0; mi < 2; mi++)
#pragma unroll
            for (int ni = 0; ni < 8; ni++)
#pragma unroll
                for (int j = 0; j < 4; j++) cs[mi][ni][j] = 0.f;

#pragma unroll
        for (int ks = 0; ks < 4; ks++) {
            uint32_t a[2][4], bf[8][2];
#pragma unroll
            for (int mi = 0; mi < 2; mi++) {
                int row = wm + (mi << 4) + g;
                a[mi][0] = *(const uint32_t*)&Qs[(row    ) * HP + (ks << 4) + (t << 1)];
                a[mi][1] = *(const uint32_t*)&Qs[(row + 8) * HP + (ks << 4) + (t << 1)];
                a[mi][2] = *(const uint32_t*)&Qs[(row    ) * HP + (ks << 4) + 8 + (t << 1)];
                a[mi][3] = *(const uint32_t*)&Qs[(row + 8) * HP + (ks << 4) + 8 + (t << 1)];
            }
#pragma unroll
            for (int ni = 0; ni < 8; ni++) {
                int key = (ni << 3) + g;
                bf[ni][0] = *(const uint32_t*)&Kst[key * HP + (ks << 4) + (t << 1)];
                bf[ni][1] = *(const uint32_t*)&Kst[key * HP + (ks << 4) + 8 + (t << 1)];
            }
#pragma unroll
            for (int mi = 0; mi < 2; mi++)
#pragma unroll
                for (int ni = 0; ni < 8; ni++)
                    mma_f16(cs[mi][ni], a[mi], bf[ni]);
        }

        // ---- scale + causal mask ----
        const bool need_mask = (kt >= 2 * qt);
#pragma unroll
        for (int mi = 0; mi < 2; mi++)
#pragma unroll
            for (int ni = 0; ni < 8; ni++)
#pragma unroll
                for (int j = 0; j < 4; j++) {
                    float s = cs[mi][ni][j] * 0.125f;
                    if (need_mask) {
                        int row = qt * 128 + wm + (mi << 4) + g + ((j >> 1) << 3);
                        int col = kt * 64 + (ni << 3) + (t << 1) + (j & 1);
                        if (col > row) s = -1e9f;
                    }
                    cs[mi][ni][j] = s;
                }

        // ---- online softmax ----
        float mt[2][2];
#pragma unroll
        for (int mi = 0; mi < 2; mi++)
#pragma unroll
            for (int hh = 0; hh < 2; hh++) {
                float mx = -INFINITY;
#pragma unroll
                for (int ni = 0; ni < 8; ni++)
                    mx = fmaxf(mx, fmaxf(cs[mi][ni][2*hh], cs[mi][ni][2*hh+1]));
                mx = fmaxf(mx, __shfl_xor_sync(0xffffffffu, mx, 1));
                mx = fmaxf(mx, __shfl_xor_sync(0xffffffffu, mx, 2));
                mt[mi][hh] = mx;
            }

        float al[2][2], mn[2][2];
#pragma unroll
        for (int mi = 0; mi < 2; mi++)
#pragma unroll
            for (int hh = 0; hh < 2; hh++) {
                float m2 = fmaxf(m_i[mi][hh], mt[mi][hh]);
                al[mi][hh] = __expf(m_i[mi][hh] - m2);
                m_i[mi][hh] = m2;
                mn[mi][hh] = m2;
            }

        float rs[2][2] = {{0.f,0.f},{0.f,0.f}};
#pragma unroll
        for (int mi = 0; mi < 2; mi++)
#pragma unroll
            for (int ni = 0; ni < 8; ni++)
#pragma unroll
                for (int j = 0; j < 4; j++) {
                    int hh = j >> 1;
                    float e = __expf(cs[mi][ni][j] - mn[mi][hh]);
                    cs[mi][ni][j] = e;
                    rs[mi][hh] += e;
                }
#pragma unroll
        for (int mi = 0; mi < 2; mi++)
#pragma unroll
            for (int hh = 0; hh < 2; hh++) {
                float r = rs[mi][hh];
                r += __shfl_xor_sync(0xffffffffu, r, 1);
                r += __shfl_xor_sync(0xffffffffu, r, 2);
                l_i[mi][hh] = l_i[mi][hh] * al[mi][hh] + r;
            }
#pragma unroll
        for (int mi = 0; mi < 2; mi++)
#pragma unroll
            for (int ni = 0; ni < 8; ni++)
#pragma unroll
                for (int j = 0; j < 4; j++)
                    co[mi][ni][j] *= al[mi][j >> 1];

        // ---- store P (half) to warp-private rows ----
#pragma unroll
        for (int mi = 0; mi < 2; mi++) {
            int row = wm + (mi << 4) + g;
#pragma unroll
            for (int ni = 0; ni < 8; ni++) {
                int col = (ni << 3) + (t << 1);
                *(uint32_t*)&Ps[(row    ) * HP + col] = pkh2(cs[mi][ni][0], cs[mi][ni][1]);
                *(uint32_t*)&Ps[(row + 8) * HP + col] = pkh2(cs[mi][ni][2], cs[mi][ni][3]);
            }
        }
        __syncwarp();

        // ---- O += P @ V  (V via ldmatrix.x4.trans) ----
#pragma unroll
        for (int ks = 0; ks < 4; ks++) {
            uint32_t a[2][4], bf[8][2];
#pragma unroll
            for (int mi = 0; mi < 2; mi++) {
                int row = wm + (mi << 4) + g;
                a[mi][0] = *(const uint32_t*)&Ps[(row    ) * HP + (ks << 4) + (t << 1)];
                a[mi][1] = *(const uint32_t*)&Ps[(row + 8) * HP + (ks << 4) + (t << 1)];
                a[mi][2] = *(const uint32_t*)&Ps[(row    ) * HP + (ks << 4) + 8 + (t << 1)];
                a[mi][3] = *(const uint32_t*)&Ps[(row + 8) * HP + (ks << 4) + 8 + (t << 1)];
            }
#pragma unroll
            for (int nn = 0; nn < 4; nn++) {
                uint32_t addr = vtile + (((ks << 4) + vrow) * HP + (nn << 4) + vcol) * 2;
                ldsm4t(bf[2*nn][0], bf[2*nn][1], bf[2*nn+1][0], bf[2*nn+1][1], addr);
            }
#pragma unroll
            for (int mi = 0; mi < 2; mi++)
#pragma unroll
                for (int ni = 0; ni < 8; ni++)
                    mma_f16(co[mi][ni], a[mi], bf[ni]);
        }
    }

    // ---- epilogue ----
#pragma unroll
    for (int mi = 0; mi < 2; mi++)
#pragma unroll
        for (int hh = 0; hh < 2; hh++) {
            float inv = 1.f / l_i[mi][hh];
            int row = qt * 128 + wm + (mi << 4) + g + (hh << 3);
            __half* ob = O + ((size_t)(b * SS + row)) * DD + h * DKH;
#pragma unroll
            for (int ni = 0; ni < 8; ni++) {
                int col = (ni << 3) + (t << 1);
                *(uint32_t*)(ob + col) = pkh2(co[mi][ni][2*hh] * inv,
                                              co[mi][ni][2*hh+1] * inv);
            }
        }
}

// =============================================================================
// Launch
// =============================================================================
extern "C" void kernel_launch(void* const* d_in, const int* in_sizes, int n_in,
                              void* d_out, int out_size)
{
    const float* q  = (const float*)d_in[1];
    const float* k  = (const float*)d_in[2];
    const float* v  = (const float*)d_in[3];
    const float* wq = (const float*)d_in[5];
    const float* bq = (const float*)d_in[6];
    const float* wk = (const float*)d_in[7];
    const float* bk = (const float*)d_in[8];
    const float* wv = (const float*)d_in[9];
    const float* bv = (const float*)d_in[10];
    const float* wo = (const float*)d_in[11];
    const float* bo = (const float*)d_in[12];
    float* out = (float*)d_out;

    __half *aq, *ak, *av, *qh, *kh, *vh, *aoh, *wtq, *wtk, *wtv, *wto;
    cudaGetSymbolAddress((void**)&aq,  g_Aq);
    cudaGetSymbolAddress((void**)&ak,  g_Ak);
    cudaGetSymbolAddress((void**)&av,  g_Av);
    cudaGetSymbolAddress((void**)&qh,  g_Qh);
    cudaGetSymbolAddress((void**)&kh,  g_Kh);
    cudaGetSymbolAddress((void**)&vh,  g_Vh);
    cudaGetSymbolAddress((void**)&aoh, g_AOh);
    cudaGetSymbolAddress((void**)&wtq, g_Wq);
    cudaGetSymbolAddress((void**)&wtk, g_Wk);
    cudaGetSymbolAddress((void**)&wtv, g_Wv);
    cudaGetSymbolAddress((void**)&wto, g_Wo);

    cudaFuncSetAttribute(flash_f16_kernel,
                         cudaFuncAttributeMaxDynamicSharedMemorySize, ATT_SMEM);
    cudaFuncSetAttribute(gemm_qkv_f16,
                         cudaFuncAttributeMaxDynamicSharedMemorySize, G_SMEM);
    cudaFuncSetAttribute(gemm_o_f16,
                         cudaFuncAttributeMaxDynamicSharedMemorySize, G_SMEM);

    // ---- prepass (2 launches) ----
    const int nA4 = MTOT * DD / 4;
    act_conv_kernel<<<dim3(nA4 / 256, 3), 256>>>(q, k, v, aq, ak, av);
    wt_trans_kernel<<<dim3(DD / 32, DD / 32, 4), dim3(32, 8)>>>(
        wq, wk, wv, wo, wtq, wtk, wtv, wto);

    // ---- fused QKV projections (one launch) ----
    dim3 gblk(256);
    dim3 gqkv(DD / 128, MTOT / 128, 3);   // (8, 64, 3)
    gemm_qkv_f16<<<gqkv, gblk, G_SMEM>>>(aq, ak, av, wtq, wtk, wtv,
                                         bq, bk, bv, qh, kh, vh);

    // ---- attention ----
    dim3 agrid(SS / 128, HH, BB);         // (16, 16, 4)
    flash_f16_kernel<<<agrid, dim3(128), ATT_SMEM>>>(qh, kh, vh, aoh);

    // ---- output projection (fp32 out) ----
    dim3 go(DD / 128, MTOT / 128);
    gemm_o_f16<<<go, gblk, G_SMEM>>>(aoh, wto, bo, out);
}

// round 9
// speedup vs baseline: 2.0946x; 1.0476x over previous
#include <cuda_runtime.h>
#include <cuda_fp16.h>
#include <math.h>
#include <stdint.h>

// Problem constants
#define BB 4
#define SS 2048
#define DD 1024
#define HH 16
#define DKH 64
#define MTOT (BB*SS)          // 8192 rows

#define L2E 1.4426950408889634f

// ---------------- scratch (static device globals; no allocation) -------------
__device__ __half g_Aq[MTOT*DD];   // half-converted inputs
__device__ __half g_Ak[MTOT*DD];
__device__ __half g_Av[MTOT*DD];
__device__ __half g_Qh[MTOT*DD];   // projection outputs (half)
__device__ __half g_Kh[MTOT*DD];
__device__ __half g_Vh[MTOT*DD];
__device__ __half g_AOh[MTOT*DD];  // attention output (half)
__device__ __half g_Wq[DD*DD];     // WT[n][k] half (wq pre-scaled by 0.125)
__device__ __half g_Wk[DD*DD];
__device__ __half g_Wv[DD*DD];
__device__ __half g_Wo[DD*DD];

// ---------------- helpers -----------------------------------------------------
__device__ __forceinline__ uint32_t pkh2(float a, float b) {
    __half2 h = __floats2half2_rn(a, b);
    return *(uint32_t*)&h;
}
__device__ __forceinline__ uint32_t ex2h2(uint32_t x) {
    uint32_t r;
    asm("ex2.approx.f16x2 %0, %1;" : "=r"(r) : "r"(x));
    return r;
}
__device__ __forceinline__ void cpa16(uint32_t smem, const void* gmem) {
    asm volatile("cp.async.cg.shared.global [%0], [%1], 16;" :: "r"(smem), "l"(gmem));
}
__device__ __forceinline__ void cpa_commit() {
    asm volatile("cp.async.commit_group;");
}
template<int N> __device__ __forceinline__ void cpa_wait() {
    asm volatile("cp.async.wait_group %0;" :: "n"(N));
}
__device__ __forceinline__ uint32_t smem_u32(const void* p) {
    uint32_t a;
    asm("{ .reg .u64 t; cvta.to.shared.u64 t, %1; cvt.u32.u64 %0, t; }"
        : "=r"(a) : "l"(p));
    return a;
}
__device__ __forceinline__ void mma_f16(
    float c[4], const uint32_t a[4], const uint32_t b[2])
{
    asm volatile(
        "mma.sync.aligned.m16n8k16.row.col.f32.f16.f16.f32 "
        "{%0,%1,%2,%3}, {%4,%5,%6,%7}, {%8,%9}, {%0,%1,%2,%3};"
        : "+f"(c[0]), "+f"(c[1]), "+f"(c[2]), "+f"(c[3])
        : "r"(a[0]), "r"(a[1]), "r"(a[2]), "r"(a[3]),
          "r"(b[0]), "r"(b[1]));
}
__device__ __forceinline__ void ldsm4t(
    uint32_t& r0, uint32_t& r1, uint32_t& r2, uint32_t& r3, uint32_t a)
{
    asm volatile("ldmatrix.sync.aligned.m8n8.x4.trans.shared.b16 {%0,%1,%2,%3}, [%4];"
                 : "=r"(r0), "=r"(r1), "=r"(r2), "=r"(r3) : "r"(a));
}

// ---------------- prepass kernels (merged) ------------------------------------
__global__ __launch_bounds__(256) void act_conv_kernel(
    const float* __restrict__ q, const float* __restrict__ k,
    const float* __restrict__ v,
    __half* __restrict__ oq, __half* __restrict__ ok, __half* __restrict__ ov)
{
    const int which = blockIdx.y;
    const float* in = (which == 0) ? q : (which == 1) ? k : v;
    __half* out     = (which == 0) ? oq : (which == 1) ? ok : ov;
    int i = blockIdx.x * blockDim.x + threadIdx.x;
    float4 vv = ((const float4*)in)[i];
    uint2 o;
    o.x = pkh2(vv.x, vv.y);
    o.y = pkh2(vv.z, vv.w);
    ((uint2*)out)[i] = o;
}

// WT[n][k] = half(W[k][n] * scale); wq gets scale 0.125 (softmax 1/sqrt(dk))
__global__ __launch_bounds__(256) void wt_trans_kernel(
    const float* __restrict__ wq, const float* __restrict__ wk,
    const float* __restrict__ wv, const float* __restrict__ wo,
    __half* __restrict__ oq, __half* __restrict__ ok,
    __half* __restrict__ ov, __half* __restrict__ oo)
{
    const int which = blockIdx.z;
    const float* in = (which == 0) ? wq : (which == 1) ? wk : (which == 2) ? wv : wo;
    __half* out     = (which == 0) ? oq : (which == 1) ? ok : (which == 2) ? ov : oo;
    const float sc  = (which == 0) ? 0.125f : 1.0f;

    __shared__ float tl[32][33];
    const int tx = threadIdx.x, ty = threadIdx.y;
    const int n0 = blockIdx.x * 32, k0 = blockIdx.y * 32;
#pragma unroll
    for (int i = 0; i < 4; i++)
        tl[ty + i * 8][tx] = in[(size_t)(k0 + ty + i * 8) * DD + n0 + tx];
    __syncthreads();
#pragma unroll
    for (int i = 0; i < 4; i++)
        out[(size_t)(n0 + ty + i * 8) * DD + k0 + tx] =
            __float2half(tl[tx][ty + i * 8] * sc);
}

// =============================================================================
// FP16 HMMA GEMM (fused QKV): C = A @ WT^T + bias. blockIdx.z selects inputs.
// Q projection (z=0) bias scaled by 0.125 (weights pre-scaled in prepass).
// =============================================================================
#define HP 72
#define G_STG_H (2 * 128 * HP)
#define G_SMEM (3 * G_STG_H * 2)          // 110592 bytes
#define GNT (DD / 64)                     // 16 K-iterations

__global__ __launch_bounds__(256) void gemm_qkv_f16(
    const __half* __restrict__ A0, const __half* __restrict__ A1,
    const __half* __restrict__ A2,
    const __half* __restrict__ W0, const __half* __restrict__ W1,
    const __half* __restrict__ W2,
    const float* __restrict__ b0, const float* __restrict__ b1,
    const float* __restrict__ b2,
    __half* __restrict__ C0, __half* __restrict__ C1, __half* __restrict__ C2)
{
    extern __shared__ __half shh[];

    const int z = blockIdx.z;
    const __half* A  = (z == 0) ? A0 : (z == 1) ? A1 : A2;
    const __half* WT = (z == 0) ? W0 : (z == 1) ? W1 : W2;
    const float* bias = (z == 0) ? b0 : (z == 1) ? b1 : b2;
    __half* C        = (z == 0) ? C0 : (z == 1) ? C1 : C2;
    const float bsc  = (z == 0) ? 0.125f : 1.0f;

    const int tid  = threadIdx.x;
    const int wid  = tid >> 5;
    const int lane = tid & 31;
    const int g    = lane >> 2;
    const int t    = lane & 3;
    const int wm   = (wid & 3) << 5;
    const int wn   = (wid >> 2) << 6;
    const int m0   = blockIdx.y << 7;
    const int n0   = blockIdx.x << 7;

    float c[2][8][4];
#pragma unroll
    for (int mi = 0; mi < 2; mi++)
#pragma unroll
        for (int ni = 0; ni < 8; ni++)
#pragma unroll
            for (int j = 0; j < 4; j++) c[mi][ni][j] = 0.f;

    const uint32_t shbase = smem_u32(shh);

    auto load_tile = [&](int kt, int stg) {
        const int k0 = kt << 6;
        const uint32_t sa = shbase + (stg * G_STG_H) * 2;
        const uint32_t sb = sa + 128 * HP * 2;
#pragma unroll
        for (int j = 0; j < 4; j++) {
            int ca = j * 256 + tid;
            int row = ca >> 3, k8 = ca & 7;
            cpa16(sa + (row * HP + (k8 << 3)) * 2,
                  A + (size_t)(m0 + row) * DD + k0 + (k8 << 3));
        }
#pragma unroll
        for (int j = 0; j < 4; j++) {
            int cb = j * 256 + tid;
            int row = cb >> 3, k8 = cb & 7;
            cpa16(sb + (row * HP + (k8 << 3)) * 2,
                  WT + (size_t)(n0 + row) * DD + k0 + (k8 << 3));
        }
        cpa_commit();
    };

    load_tile(0, 0);
    load_tile(1, 1);

    for (int kt = 0; kt < GNT; kt++) {
        if (kt + 1 < GNT) cpa_wait<1>(); else cpa_wait<0>();
        __syncthreads();
        if (kt + 2 < GNT) load_tile(kt + 2, (kt + 2) % 3);

        const int stg = kt % 3;
        const __half* as = shh + stg * G_STG_H;
        const __half* bs = as + 128 * HP;

#pragma unroll
        for (int ks = 0; ks < 4; ks++) {
            uint32_t a[2][4], b[8][2];
#pragma unroll
            for (int mi = 0; mi < 2; mi++) {
                int mr = wm + (mi << 4) + g;
                a[mi][0] = *(const uint32_t*)&as[(mr    ) * HP + (ks << 4) + (t << 1)];
                a[mi][1] = *(const uint32_t*)&as[(mr + 8) * HP + (ks << 4) + (t << 1)];
                a[mi][2] = *(const uint32_t*)&as[(mr    ) * HP + (ks << 4) + 8 + (t << 1)];
                a[mi][3] = *(const uint32_t*)&as[(mr + 8) * HP + (ks << 4) + 8 + (t << 1)];
            }
#pragma unroll
            for (int ni = 0; ni < 8; ni++) {
                int nc = wn + (ni << 3) + g;
                b[ni][0] = *(const uint32_t*)&bs[nc * HP + (ks << 4) + (t << 1)];
                b[ni][1] = *(const uint32_t*)&bs[nc * HP + (ks << 4) + 8 + (t << 1)];
            }
#pragma unroll
            for (int mi = 0; mi < 2; mi++)
#pragma unroll
                for (int ni = 0; ni < 8; ni++)
                    mma_f16(c[mi][ni], a[mi], b[ni]);
        }
    }

#pragma unroll
    for (int ni = 0; ni < 8; ni++) {
        int col = n0 + wn + (ni << 3) + (t << 1);
        float2 bv = *(const float2*)(bias + col);
        bv.x *= bsc; bv.y *= bsc;
#pragma unroll
        for (int mi = 0; mi < 2; mi++) {
            int row = m0 + wm + (mi << 4) + g;
            *(uint32_t*)(C + (size_t)row       * DD + col) =
                pkh2(c[mi][ni][0] + bv.x, c[mi][ni][1] + bv.y);
            *(uint32_t*)(C + (size_t)(row + 8) * DD + col) =
                pkh2(c[mi][ni][2] + bv.x, c[mi][ni][3] + bv.y);
        }
    }
}

// Single GEMM (output projection, fp32 out) — same core.
__global__ __launch_bounds__(256) void gemm_o_f16(
    const __half* __restrict__ A, const __half* __restrict__ WT,
    const float* __restrict__ bias, float* __restrict__ C)
{
    extern __shared__ __half shh[];

    const int tid  = threadIdx.x;
    const int wid  = tid >> 5;
    const int lane = tid & 31;
    const int g    = lane >> 2;
    const int t    = lane & 3;
    const int wm   = (wid & 3) << 5;
    const int wn   = (wid >> 2) << 6;
    const int m0   = blockIdx.y << 7;
    const int n0   = blockIdx.x << 7;

    float c[2][8][4];
#pragma unroll
    for (int mi = 0; mi < 2; mi++)
#pragma unroll
        for (int ni = 0; ni < 8; ni++)
#pragma unroll
            for (int j = 0; j < 4; j++) c[mi][ni][j] = 0.f;

    const uint32_t shbase = smem_u32(shh);

    auto load_tile = [&](int kt, int stg) {
        const int k0 = kt << 6;
        const uint32_t sa = shbase + (stg * G_STG_H) * 2;
        const uint32_t sb = sa + 128 * HP * 2;
#pragma unroll
        for (int j = 0; j < 4; j++) {
            int ca = j * 256 + tid;
            int row = ca >> 3, k8 = ca & 7;
            cpa16(sa + (row * HP + (k8 << 3)) * 2,
                  A + (size_t)(m0 + row) * DD + k0 + (k8 << 3));
        }
#pragma unroll
        for (int j = 0; j < 4; j++) {
            int cb = j * 256 + tid;
            int row = cb >> 3, k8 = cb & 7;
            cpa16(sb + (row * HP + (k8 << 3)) * 2,
                  WT + (size_t)(n0 + row) * DD + k0 + (k8 << 3));
        }
        cpa_commit();
    };

    load_tile(0, 0);
    load_tile(1, 1);

    for (int kt = 0; kt < GNT; kt++) {
        if (kt + 1 < GNT) cpa_wait<1>(); else cpa_wait<0>();
        __syncthreads();
        if (kt + 2 < GNT) load_tile(kt + 2, (kt + 2) % 3);

        const int stg = kt % 3;
        const __half* as = shh + stg * G_STG_H;
        const __half* bs = as + 128 * HP;

#pragma unroll
        for (int ks = 0; ks < 4; ks++) {
            uint32_t a[2][4], b[8][2];
#pragma unroll
            for (int mi = 0; mi < 2; mi++) {
                int mr = wm + (mi << 4) + g;
                a[mi][0] = *(const uint32_t*)&as[(mr    ) * HP + (ks << 4) + (t << 1)];
                a[mi][1] = *(const uint32_t*)&as[(mr + 8) * HP + (ks << 4) + (t << 1)];
                a[mi][2] = *(const uint32_t*)&as[(mr    ) * HP + (ks << 4) + 8 + (t << 1)];
                a[mi][3] = *(const uint32_t*)&as[(mr + 8) * HP + (ks << 4) + 8 + (t << 1)];
            }
#pragma unroll
            for (int ni = 0; ni < 8; ni++) {
                int nc = wn + (ni << 3) + g;
                b[ni][0] = *(const uint32_t*)&bs[nc * HP + (ks << 4) + (t << 1)];
                b[ni][1] = *(const uint32_t*)&bs[nc * HP + (ks << 4) + 8 + (t << 1)];
            }
#pragma unroll
            for (int mi = 0; mi < 2; mi++)
#pragma unroll
                for (int ni = 0; ni < 8; ni++)
                    mma_f16(c[mi][ni], a[mi], b[ni]);
        }
    }

#pragma unroll
    for (int ni = 0; ni < 8; ni++) {
        int col = n0 + wn + (ni << 3) + (t << 1);
        float2 bv = *(const float2*)(bias + col);
#pragma unroll
        for (int mi = 0; mi < 2; mi++) {
            int row = m0 + wm + (mi << 4) + g;
            float2 v0 = make_float2(c[mi][ni][0] + bv.x, c[mi][ni][1] + bv.y);
            float2 v1 = make_float2(c[mi][ni][2] + bv.x, c[mi][ni][3] + bv.y);
            *(float2*)(C + (size_t)row       * DD + col) = v0;
            *(float2*)(C + (size_t)(row + 8) * DD + col) = v1;
        }
    }
}

// =============================================================================
// FP16 flash attention (causal), cp.async double-buffered K/V.
// Softmax: scale folded into wq; exp via ex2.approx.f16x2; row-sum l via
// MMA against a ones operand (exact fp32 sum of the same half P used in PV).
// =============================================================================
#define ATT_SMEM ((128*HP + 2*64*HP + 2*64*HP + 128*HP) * 2)

__global__ __launch_bounds__(128) void flash_f16_kernel(
    const __half* __restrict__ Q, const __half* __restrict__ K,
    const __half* __restrict__ V, __half* __restrict__ O)
{
    const int qt = (SS / 128 - 1) - blockIdx.x;   // heavy blocks first
    const int h  = blockIdx.y;
    const int b  = blockIdx.z;
    const int tid  = threadIdx.x;
    const int warp = tid >> 5;
    const int lane = tid & 31;
    const int g    = lane >> 2;
    const int t    = lane & 3;
    const int wm   = warp << 5;

    extern __shared__ __half smh[];
    __half* Qs = smh;                    // [128][HP]
    __half* Ks = Qs + 128 * HP;          // [2][64][HP]
    __half* Vs = Ks + 2 * 64 * HP;       // [2][64][HP]
    __half* Ps = Vs + 2 * 64 * HP;       // [128][HP]

    const uint32_t ksbase = smem_u32(Ks);
    const uint32_t vsbase = smem_u32(Vs);

    const int vrow = ((lane >> 3) & 1) * 8 + (lane & 7);
    const int vcol = (lane >> 4) * 8;

    const __half* Kh0 = K + ((size_t)(b * SS)) * DD + h * DKH;
    const __half* Vh0 = V + ((size_t)(b * SS)) * DD + h * DKH;

    auto load_kv = [&](int kt, int buf) {
        const __half* Kb = Kh0 + (size_t)(kt * 64) * DD;
        const __half* Vb = Vh0 + (size_t)(kt * 64) * DD;
        const uint32_t kb = ksbase + buf * 64 * HP * 2;
        const uint32_t vb = vsbase + buf * 64 * HP * 2;
#pragma unroll
        for (int i = 0; i < 4; i++) {
            int e = i * 128 + tid;
            int r = e >> 3;
            int c8 = e & 7;
            cpa16(kb + (r * HP + (c8 << 3)) * 2, Kb + (size_t)r * DD + (c8 << 3));
            cpa16(vb + (r * HP + (c8 << 3)) * 2, Vb + (size_t)r * DD + (c8 << 3));
        }
        cpa_commit();
    };

    // ---- load Q tile ----
    const __half* Qb = Q + ((size_t)(b * SS + qt * 128)) * DD + h * DKH;
#pragma unroll
    for (int i = 0; i < 8; i++) {
        int e = i * 128 + tid;
        int r = e >> 3;
        int c8 = e & 7;
        *(uint4*)&Qs[r * HP + (c8 << 3)] = *(const uint4*)(Qb + (size_t)r * DD + (c8 << 3));
    }

    load_kv(0, 0);

    float m_i[2][2], l_i[2][2], co[2][8][4];
#pragma unroll
    for (int mi = 0; mi < 2; mi++)
#pragma unroll
        for (int hh = 0; hh < 2; hh++) { m_i[mi][hh] = -INFINITY; l_i[mi][hh] = 0.f; }
#pragma unroll
    for (int mi = 0; mi < 2; mi++)
#pragma unroll
        for (int ni = 0; ni < 8; ni++)
#pragma unroll
            for (int j = 0; j < 4; j++) co[mi][ni][j] = 0.f;

    const uint32_t bones = 0x3C003C00u;  // half2(1,1)
    const int ktmax = 2 * qt + 1;

    for (int kt = 0; kt <= ktmax; kt++) {
        __syncthreads();
        if (kt < ktmax) {
            load_kv(kt + 1, (kt + 1) & 1);
            cpa_wait<1>();
        } else {
            cpa_wait<0>();
        }
        __syncthreads();

        const __half* Kst = Ks + (kt & 1) * 64 * HP;
        const uint32_t vtile = vsbase + (kt & 1) * 64 * HP * 2;

        // ---- S = Q K^T  (already scaled by 1/8 via wq) ----
        float cs[2][8][4];
#pragma unroll
        for (int mi = 0; mi < 2; mi++)
#pragma unroll
            for (int ni = 0; ni < 8; ni++)
#pragma unroll
                for (int j = 0; j < 4; j++) cs[mi][ni][j] = 0.f;

#pragma unroll
        for (int ks = 0; ks < 4; ks++) {
            uint32_t a[2][4], bf[8][2];
#pragma unroll
            for (int mi = 0; mi < 2; mi++) {
                int row = wm + (mi << 4) + g;
                a[mi][0] = *(const uint32_t*)&Qs[(row    ) * HP + (ks << 4) + (t << 1)];
                a[mi][1] = *(const uint32_t*)&Qs[(row + 8) * HP + (ks << 4) + (t << 1)];
                a[mi][2] = *(const uint32_t*)&Qs[(row    ) * HP + (ks << 4) + 8 + (t << 1)];
                a[mi][3] = *(const uint32_t*)&Qs[(row + 8) * HP + (ks << 4) + 8 + (t << 1)];
            }
#pragma unroll
            for (int ni = 0; ni < 8; ni++) {
                int key = (ni << 3) + g;
                bf[ni][0] = *(const uint32_t*)&Kst[key * HP + (ks << 4) + (t << 1)];
                bf[ni][1] = *(const uint32_t*)&Kst[key * HP + (ks << 4) + 8 + (t << 1)];
            }
#pragma unroll
            for (int mi = 0; mi < 2; mi++)
#pragma unroll
                for (int ni = 0; ni < 8; ni++)
                    mma_f16(cs[mi][ni], a[mi], bf[ni]);
        }

        // ---- causal mask (only last two tiles of this CTA) ----
        if (kt >= 2 * qt) {
#pragma unroll
            for (int mi = 0; mi < 2; mi++)
#pragma unroll
                for (int ni = 0; ni < 8; ni++)
#pragma unroll
                    for (int j = 0; j < 4; j++) {
                        int row = qt * 128 + wm + (mi << 4) + g + ((j >> 1) << 3);
                        int col = kt * 64 + (ni << 3) + (t << 1) + (j & 1);
                        if (col > row) cs[mi][ni][j] = -1e9f;
                    }
        }

        // ---- online softmax: max, alpha ----
        float ml[2][2], al[2][2];
#pragma unroll
        for (int mi = 0; mi < 2; mi++)
#pragma unroll
            for (int hh = 0; hh < 2; hh++) {
                float mx = -INFINITY;
#pragma unroll
                for (int ni = 0; ni < 8; ni++)
                    mx = fmaxf(mx, fmaxf(cs[mi][ni][2*hh], cs[mi][ni][2*hh+1]));
                mx = fmaxf(mx, __shfl_xor_sync(0xffffffffu, mx, 1));
                mx = fmaxf(mx, __shfl_xor_sync(0xffffffffu, mx, 2));
                float m2 = fmaxf(m_i[mi][hh], mx);
                al[mi][hh] = __expf(m_i[mi][hh] - m2);
                m_i[mi][hh] = m2;
                ml[mi][hh] = m2 * L2E;
            }
#pragma unroll
        for (int mi = 0; mi < 2; mi++)
#pragma unroll
            for (int ni = 0; ni < 8; ni++)
#pragma unroll
                for (int j = 0; j < 4; j++)
                    co[mi][ni][j] *= al[mi][j >> 1];

        // ---- P = exp(S - m) directly in half via ex2.f16x2; store to smem ----
#pragma unroll
        for (int mi = 0; mi < 2; mi++) {
            int row = wm + (mi << 4) + g;
#pragma unroll
            for (int ni = 0; ni < 8; ni++) {
                int col = (ni << 3) + (t << 1);
                float u0 = fmaf(cs[mi][ni][0], L2E, -ml[mi][0]);
                float u1 = fmaf(cs[mi][ni][1], L2E, -ml[mi][0]);
                float u2 = fmaf(cs[mi][ni][2], L2E, -ml[mi][1]);
                float u3 = fmaf(cs[mi][ni][3], L2E, -ml[mi][1]);
                *(uint32_t*)&Ps[(row    ) * HP + col] = ex2h2(pkh2(u0, u1));
                *(uint32_t*)&Ps[(row + 8) * HP + col] = ex2h2(pkh2(u2, u3));
            }
        }
        __syncwarp();

        // ---- O += P @ V  and  l-rowsum via MMA with ones ----
        float csum[2][4];
#pragma unroll
        for (int mi = 0; mi < 2; mi++)
#pragma unroll
            for (int j = 0; j < 4; j++) csum[mi][j] = 0.f;

#pragma unroll
        for (int ks = 0; ks < 4; ks++) {
            uint32_t a[2][4], bf[8][2];
#pragma unroll
            for (int mi = 0; mi < 2; mi++) {
                int row = wm + (mi << 4) + g;
                a[mi][0] = *(const uint32_t*)&Ps[(row    ) * HP + (ks << 4) + (t << 1)];
                a[mi][1] = *(const uint32_t*)&Ps[(row + 8) * HP + (ks << 4) + (t << 1)];
                a[mi][2] = *(const uint32_t*)&Ps[(row    ) * HP + (ks << 4) + 8 + (t << 1)];
                a[mi][3] = *(const uint32_t*)&Ps[(row + 8) * HP + (ks << 4) + 8 + (t << 1)];
            }
#pragma unroll
            for (int nn = 0; nn < 4; nn++) {
                uint32_t addr = vtile + (((ks << 4) + vrow) * HP + (nn << 4) + vcol) * 2;
                ldsm4t(bf[2*nn][0], bf[2*nn][1], bf[2*nn+1][0], bf[2*nn+1][1], addr);
            }
#pragma unroll
            for (int mi = 0; mi < 2; mi++) {
                uint32_t bo[2] = {bones, bones};
                mma_f16(csum[mi], a[mi], bo);
#pragma unroll
                for (int ni = 0; ni < 8; ni++)
                    mma_f16(co[mi][ni], a[mi], bf[ni]);
            }
        }

#pragma unroll
        for (int mi = 0; mi < 2; mi++)
#pragma unroll
            for (int hh = 0; hh < 2; hh++)
                l_i[mi][hh] = l_i[mi][hh] * al[mi][hh] + csum[mi][2*hh];
    }

    // ---- epilogue ----
#pragma unroll
    for (int mi = 0; mi < 2; mi++)
#pragma unroll
        for (int hh = 0; hh < 2; hh++) {
            float inv = 1.f / l_i[mi][hh];
            int row = qt * 128 + wm + (mi << 4) + g + (hh << 3);
            __half* ob = O + ((size_t)(b * SS + row)) * DD + h * DKH;
#pragma unroll
            for (int ni = 0; ni < 8; ni++) {
                int col = (ni << 3) + (t << 1);
                *(uint32_t*)(ob + col) = pkh2(co[mi][ni][2*hh] * inv,
                                              co[mi][ni][2*hh+1] * inv);
            }
        }
}

// =============================================================================
// Launch
// =============================================================================
extern "C" void kernel_launch(void* const* d_in, const int* in_sizes, int n_in,
                              void* d_out, int out_size)
{
    const float* q  = (const float*)d_in[1];
    const float* k  = (const float*)d_in[2];
    const float* v  = (const float*)d_in[3];
    const float* wq = (const float*)d_in[5];
    const float* bq = (const float*)d_in[6];
    const float* wk = (const float*)d_in[7];
    const float* bk = (const float*)d_in[8];
    const float* wv = (const float*)d_in[9];
    const float* bv = (const float*)d_in[10];
    const float* wo = (const float*)d_in[11];
    const float* bo = (const float*)d_in[12];
    float* out = (float*)d_out;

    __half *aq, *ak, *av, *qh, *kh, *vh, *aoh, *wtq, *wtk, *wtv, *wto;
    cudaGetSymbolAddress((void**)&aq,  g_Aq);
    cudaGetSymbolAddress((void**)&ak,  g_Ak);
    cudaGetSymbolAddress((void**)&av,  g_Av);
    cudaGetSymbolAddress((void**)&qh,  g_Qh);
    cudaGetSymbolAddress((void**)&kh,  g_Kh);
    cudaGetSymbolAddress((void**)&vh,  g_Vh);
    cudaGetSymbolAddress((void**)&aoh, g_AOh);
    cudaGetSymbolAddress((void**)&wtq, g_Wq);
    cudaGetSymbolAddress((void**)&wtk, g_Wk);
    cudaGetSymbolAddress((void**)&wtv, g_Wv);
    cudaGetSymbolAddress((void**)&wto, g_Wo);

    cudaFuncSetAttribute(flash_f16_kernel,
                         cudaFuncAttributeMaxDynamicSharedMemorySize, ATT_SMEM);
    cudaFuncSetAttribute(gemm_qkv_f16,
                         cudaFuncAttributeMaxDynamicSharedMemorySize, G_SMEM);
    cudaFuncSetAttribute(gemm_o_f16,
                         cudaFuncAttributeMaxDynamicSharedMemorySize, G_SMEM);

    // ---- prepass (2 launches) ----
    const int nA4 = MTOT * DD / 4;
    act_conv_kernel<<<dim3(nA4 / 256, 3), 256>>>(q, k, v, aq, ak, av);
    wt_trans_kernel<<<dim3(DD / 32, DD / 32, 4), dim3(32, 8)>>>(
        wq, wk, wv, wo, wtq, wtk, wtv, wto);

    // ---- fused QKV projections ----
    dim3 gblk(256);
    dim3 gqkv(DD / 128, MTOT / 128, 3);   // (8, 64, 3)
    gemm_qkv_f16<<<gqkv, gblk, G_SMEM>>>(aq, ak, av, wtq, wtk, wtv,
                                         bq, bk, bv, qh, kh, vh);

    // ---- attention ----
    dim3 agrid(SS / 128, HH, BB);         // (16, 16, 4)
    flash_f16_kernel<<<agrid, dim3(128), ATT_SMEM>>>(qh, kh, vh, aoh);

    // ---- output projection (fp32 out) ----
    dim3 go(DD / 128, MTOT / 128);
    gemm_o_f16<<<go, gblk, G_SMEM>>>(aoh, wto, bo, out);
}

// round 10
// speedup vs baseline: 2.1361x; 1.0198x over previous
#include <cuda_runtime.h>
#include <cuda_fp16.h>
#include <math.h>
#include <stdint.h>

// Problem constants
#define BB 4
#define SS 2048
#define DD 1024
#define HH 16
#define DKH 64
#define MTOT (BB*SS)          // 8192 rows

#define L2E 1.4426950408889634f

// ---------------- scratch (static device globals; no allocation) -------------
__device__ __half g_Aq[MTOT*DD];
__device__ __half g_Ak[MTOT*DD];
__device__ __half g_Av[MTOT*DD];
__device__ __half g_Qh[MTOT*DD];
__device__ __half g_Kh[MTOT*DD];
__device__ __half g_Vh[MTOT*DD];
__device__ __half g_AOh[MTOT*DD];
__device__ __half g_Wq[DD*DD];     // WT[n][k] half (wq pre-scaled by 0.125)
__device__ __half g_Wk[DD*DD];
__device__ __half g_Wv[DD*DD];
__device__ __half g_Wo[DD*DD];

// ---------------- helpers -----------------------------------------------------
__device__ __forceinline__ uint32_t pkh2(float a, float b) {
    __half2 h = __floats2half2_rn(a, b);
    return *(uint32_t*)&h;
}
__device__ __forceinline__ uint32_t ex2h2(uint32_t x) {
    uint32_t r;
    asm("ex2.approx.f16x2 %0, %1;" : "=r"(r) : "r"(x));
    return r;
}
__device__ __forceinline__ void cpa16(uint32_t smem, const void* gmem) {
    asm volatile("cp.async.cg.shared.global [%0], [%1], 16;" :: "r"(smem), "l"(gmem));
}
__device__ __forceinline__ void cpa_commit() {
    asm volatile("cp.async.commit_group;");
}
template<int N> __device__ __forceinline__ void cpa_wait() {
    asm volatile("cp.async.wait_group %0;" :: "n"(N));
}
__device__ __forceinline__ uint32_t smem_u32(const void* p) {
    uint32_t a;
    asm("{ .reg .u64 t; cvta.to.shared.u64 t, %1; cvt.u32.u64 %0, t; }"
        : "=r"(a) : "l"(p));
    return a;
}
__device__ __forceinline__ void mma_f16(
    float c[4], const uint32_t a[4], const uint32_t b[2])
{
    asm volatile(
        "mma.sync.aligned.m16n8k16.row.col.f32.f16.f16.f32 "
        "{%0,%1,%2,%3}, {%4,%5,%6,%7}, {%8,%9}, {%0,%1,%2,%3};"
        : "+f"(c[0]), "+f"(c[1]), "+f"(c[2]), "+f"(c[3])
        : "r"(a[0]), "r"(a[1]), "r"(a[2]), "r"(a[3]),
          "r"(b[0]), "r"(b[1]));
}
// non-transposed x4 ldmatrix: r0..r3 = {rows0-7,k0-7},{rows8-15,k0-7},{rows0-7,k8-15},{rows8-15,k8-15}
__device__ __forceinline__ void ldsm4(
    uint32_t& r0, uint32_t& r1, uint32_t& r2, uint32_t& r3, uint32_t a)
{
    asm volatile("ldmatrix.sync.aligned.m8n8.x4.shared.b16 {%0,%1,%2,%3}, [%4];"
                 : "=r"(r0), "=r"(r1), "=r"(r2), "=r"(r3) : "r"(a));
}
__device__ __forceinline__ void ldsm4t(
    uint32_t& r0, uint32_t& r1, uint32_t& r2, uint32_t& r3, uint32_t a)
{
    asm volatile("ldmatrix.sync.aligned.m8n8.x4.trans.shared.b16 {%0,%1,%2,%3}, [%4];"
                 : "=r"(r0), "=r"(r1), "=r"(r2), "=r"(r3) : "r"(a));
}
__device__ __forceinline__ void stsm4(
    uint32_t a, uint32_t r0, uint32_t r1, uint32_t r2, uint32_t r3)
{
    asm volatile("stmatrix.sync.aligned.m8n8.x4.shared.b16 [%0], {%1,%2,%3,%4};"
                 :: "r"(a), "r"(r0), "r"(r1), "r"(r2), "r"(r3) : "memory");
}

// ---------------- prepass kernels (merged) ------------------------------------
__global__ __launch_bounds__(256) void act_conv_kernel(
    const float* __restrict__ q, const float* __restrict__ k,
    const float* __restrict__ v,
    __half* __restrict__ oq, __half* __restrict__ ok, __half* __restrict__ ov)
{
    const int which = blockIdx.y;
    const float* in = (which == 0) ? q : (which == 1) ? k : v;
    __half* out     = (which == 0) ? oq : (which == 1) ? ok : ov;
    int i = blockIdx.x * blockDim.x + threadIdx.x;
    float4 vv = ((const float4*)in)[i];
    uint2 o;
    o.x = pkh2(vv.x, vv.y);
    o.y = pkh2(vv.z, vv.w);
    ((uint2*)out)[i] = o;
}

// WT[n][k] = half(W[k][n] * scale); wq gets scale 0.125
__global__ __launch_bounds__(256) void wt_trans_kernel(
    const float* __restrict__ wq, const float* __restrict__ wk,
    const float* __restrict__ wv, const float* __restrict__ wo,
    __half* __restrict__ oq, __half* __restrict__ ok,
    __half* __restrict__ ov, __half* __restrict__ oo)
{
    const int which = blockIdx.z;
    const float* in = (which == 0) ? wq : (which == 1) ? wk : (which == 2) ? wv : wo;
    __half* out     = (which == 0) ? oq : (which == 1) ? ok : (which == 2) ? ov : oo;
    const float sc  = (which == 0) ? 0.125f : 1.0f;

    __shared__ float tl[32][33];
    const int tx = threadIdx.x, ty = threadIdx.y;
    const int n0 = blockIdx.x * 32, k0 = blockIdx.y * 32;
#pragma unroll
    for (int i = 0; i < 4; i++)
        tl[ty + i * 8][tx] = in[(size_t)(k0 + ty + i * 8) * DD + n0 + tx];
    __syncthreads();
#pragma unroll
    for (int i = 0; i < 4; i++)
        out[(size_t)(n0 + ty + i * 8) * DD + k0 + tx] =
            __float2half(tl[tx][ty + i * 8] * sc);
}

// =============================================================================
// FP16 HMMA GEMM (fused QKV): C = A @ WT^T + bias. blockIdx.z selects inputs.
// Fragments via ldmatrix.x4 (6 per warp-k16 instead of 24 LDS.32).
// =============================================================================
#define HP 72
#define ROWB (HP*2)                       // 144 bytes per smem row
#define G_STG_H (2 * 128 * HP)
#define G_SMEM (3 * G_STG_H * 2)          // 110592 bytes
#define GNT (DD / 64)                     // 16 K-iterations

__global__ __launch_bounds__(256) void gemm_qkv_f16(
    const __half* __restrict__ A0, const __half* __restrict__ A1,
    const __half* __restrict__ A2,
    const __half* __restrict__ W0, const __half* __restrict__ W1,
    const __half* __restrict__ W2,
    const float* __restrict__ b0, const float* __restrict__ b1,
    const float* __restrict__ b2,
    __half* __restrict__ C0, __half* __restrict__ C1, __half* __restrict__ C2)
{
    extern __shared__ __half shh[];

    const int z = blockIdx.z;
    const __half* A  = (z == 0) ? A0 : (z == 1) ? A1 : A2;
    const __half* WT = (z == 0) ? W0 : (z == 1) ? W1 : W2;
    const float* bias = (z == 0) ? b0 : (z == 1) ? b1 : b2;
    __half* C        = (z == 0) ? C0 : (z == 1) ? C1 : C2;
    const float bsc  = (z == 0) ? 0.125f : 1.0f;

    const int tid  = threadIdx.x;
    const int wid  = tid >> 5;
    const int lane = tid & 31;
    const int g    = lane >> 2;
    const int t    = lane & 3;
    const int wm   = (wid & 3) << 5;
    const int wn   = (wid >> 2) << 6;
    const int m0   = blockIdx.y << 7;
    const int n0   = blockIdx.x << 7;

    // ldmatrix per-lane address parts
    const int lj = lane >> 3, lr = lane & 7;
    uint32_t aoff[2], boff[4];
#pragma unroll
    for (int mi = 0; mi < 2; mi++)
        aoff[mi] = (uint32_t)(((wm + (mi << 4) + ((lj & 1) << 3) + lr) * HP
                               + ((lj >> 1) << 3)) * 2);
#pragma unroll
    for (int np = 0; np < 4; np++)
        boff[np] = (uint32_t)(((wn + (np << 4) + ((lj & 1) << 3) + lr) * HP
                               + ((lj >> 1) << 3)) * 2);

    float c[2][8][4];
#pragma unroll
    for (int mi = 0; mi < 2; mi++)
#pragma unroll
        for (int ni = 0; ni < 8; ni++)
#pragma unroll
            for (int j = 0; j < 4; j++) c[mi][ni][j] = 0.f;

    const uint32_t shbase = smem_u32(shh);

    auto load_tile = [&](int kt, int stg) {
        const int k0 = kt << 6;
        const uint32_t sa = shbase + (stg * G_STG_H) * 2;
        const uint32_t sb = sa + 128 * ROWB;
#pragma unroll
        for (int j = 0; j < 4; j++) {
            int ca = j * 256 + tid;
            int row = ca >> 3, k8 = ca & 7;
            cpa16(sa + row * ROWB + (k8 << 4),
                  A + (size_t)(m0 + row) * DD + k0 + (k8 << 3));
        }
#pragma unroll
        for (int j = 0; j < 4; j++) {
            int cb = j * 256 + tid;
            int row = cb >> 3, k8 = cb & 7;
            cpa16(sb + row * ROWB + (k8 << 4),
                  WT + (size_t)(n0 + row) * DD + k0 + (k8 << 3));
        }
        cpa_commit();
    };

    load_tile(0, 0);
    load_tile(1, 1);

    for (int kt = 0; kt < GNT; kt++) {
        if (kt + 1 < GNT) cpa_wait<1>(); else cpa_wait<0>();
        __syncthreads();
        if (kt + 2 < GNT) load_tile(kt + 2, (kt + 2) % 3);

        const int stg = kt % 3;
        const uint32_t sa = shbase + (stg * G_STG_H) * 2;
        const uint32_t sb = sa + 128 * ROWB;

#pragma unroll
        for (int ks = 0; ks < 4; ks++) {
            uint32_t a[2][4], b[8][2];
#pragma unroll
            for (int mi = 0; mi < 2; mi++)
                ldsm4(a[mi][0], a[mi][1], a[mi][2], a[mi][3],
                      sa + aoff[mi] + ks * 32);
#pragma unroll
            for (int np = 0; np < 4; np++)
                ldsm4(b[2*np][0], b[2*np+1][0], b[2*np][1], b[2*np+1][1],
                      sb + boff[np] + ks * 32);
#pragma unroll
            for (int mi = 0; mi < 2; mi++)
#pragma unroll
                for (int ni = 0; ni < 8; ni++)
                    mma_f16(c[mi][ni], a[mi], b[ni]);
        }
    }

#pragma unroll
    for (int ni = 0; ni < 8; ni++) {
        int col = n0 + wn + (ni << 3) + (t << 1);
        float2 bv = *(const float2*)(bias + col);
        bv.x *= bsc; bv.y *= bsc;
#pragma unroll
        for (int mi = 0; mi < 2; mi++) {
            int row = m0 + wm + (mi << 4) + g;
            *(uint32_t*)(C + (size_t)row       * DD + col) =
                pkh2(c[mi][ni][0] + bv.x, c[mi][ni][1] + bv.y);
            *(uint32_t*)(C + (size_t)(row + 8) * DD + col) =
                pkh2(c[mi][ni][2] + bv.x, c[mi][ni][3] + bv.y);
        }
    }
}

// Single GEMM (output projection, fp32 out) — same core.
__global__ __launch_bounds__(256) void gemm_o_f16(
    const __half* __restrict__ A, const __half* __restrict__ WT,
    const float* __restrict__ bias, float* __restrict__ C)
{
    extern __shared__ __half shh[];

    const int tid  = threadIdx.x;
    const int wid  = tid >> 5;
    const int lane = tid & 31;
    const int g    = lane >> 2;
    const int t    = lane & 3;
    const int wm   = (wid & 3) << 5;
    const int wn   = (wid >> 2) << 6;
    const int m0   = blockIdx.y << 7;
    const int n0   = blockIdx.x << 7;

    const int lj = lane >> 3, lr = lane & 7;
    uint32_t aoff[2], boff[4];
#pragma unroll
    for (int mi = 0; mi < 2; mi++)
        aoff[mi] = (uint32_t)(((wm + (mi << 4) + ((lj & 1) << 3) + lr) * HP
                               + ((lj >> 1) << 3)) * 2);
#pragma unroll
    for (int np = 0; np < 4; np++)
        boff[np] = (uint32_t)(((wn + (np << 4) + ((lj & 1) << 3) + lr) * HP
                               + ((lj >> 1) << 3)) * 2);

    float c[2][8][4];
#pragma unroll
    for (int mi = 0; mi < 2; mi++)
#pragma unroll
        for (int ni = 0; ni < 8; ni++)
#pragma unroll
            for (int j = 0; j < 4; j++) c[mi][ni][j] = 0.f;

    const uint32_t shbase = smem_u32(shh);

    auto load_tile = [&](int kt, int stg) {
        const int k0 = kt << 6;
        const uint32_t sa = shbase + (stg * G_STG_H) * 2;
        const uint32_t sb = sa + 128 * ROWB;
#pragma unroll
        for (int j = 0; j < 4; j++) {
            int ca = j * 256 + tid;
            int row = ca >> 3, k8 = ca & 7;
            cpa16(sa + row * ROWB + (k8 << 4),
                  A + (size_t)(m0 + row) * DD + k0 + (k8 << 3));
        }
#pragma unroll
        for (int j = 0; j < 4; j++) {
            int cb = j * 256 + tid;
            int row = cb >> 3, k8 = cb & 7;
            cpa16(sb + row * ROWB + (k8 << 4),
                  WT + (size_t)(n0 + row) * DD + k0 + (k8 << 3));
        }
        cpa_commit();
    };

    load_tile(0, 0);
    load_tile(1, 1);

    for (int kt = 0; kt < GNT; kt++) {
        if (kt + 1 < GNT) cpa_wait<1>(); else cpa_wait<0>();
        __syncthreads();
        if (kt + 2 < GNT) load_tile(kt + 2, (kt + 2) % 3);

        const int stg = kt % 3;
        const uint32_t sa = shbase + (stg * G_STG_H) * 2;
        const uint32_t sb = sa + 128 * ROWB;

#pragma unroll
        for (int ks = 0; ks < 4; ks++) {
            uint32_t a[2][4], b[8][2];
#pragma unroll
            for (int mi = 0; mi < 2; mi++)
                ldsm4(a[mi][0], a[mi][1], a[mi][2], a[mi][3],
                      sa + aoff[mi] + ks * 32);
#pragma unroll
            for (int np = 0; np < 4; np++)
                ldsm4(b[2*np][0], b[2*np+1][0], b[2*np][1], b[2*np+1][1],
                      sb + boff[np] + ks * 32);
#pragma unroll
            for (int mi = 0; mi < 2; mi++)
#pragma unroll
                for (int ni = 0; ni < 8; ni++)
                    mma_f16(c[mi][ni], a[mi], b[ni]);
        }
    }

#pragma unroll
    for (int ni = 0; ni < 8; ni++) {
        int col = n0 + wn + (ni << 3) + (t << 1);
        float2 bv = *(const float2*)(bias + col);
#pragma unroll
        for (int mi = 0; mi < 2; mi++) {
            int row = m0 + wm + (mi << 4) + g;
            float2 v0 = make_float2(c[mi][ni][0] + bv.x, c[mi][ni][1] + bv.y);
            float2 v1 = make_float2(c[mi][ni][2] + bv.x, c[mi][ni][3] + bv.y);
            *(float2*)(C + (size_t)row       * DD + col) = v0;
            *(float2*)(C + (size_t)(row + 8) * DD + col) = v1;
        }
    }
}

// =============================================================================
// FP16 flash attention (causal): ldmatrix for Q/K/P fragments, stmatrix for
// P store, ex2.f16x2 softmax, row-sum via MMA with ones, cp.async K/V.
// =============================================================================
#define ATT_SMEM ((128*HP + 2*64*HP + 2*64*HP + 128*HP) * 2)

__global__ __launch_bounds__(128) void flash_f16_kernel(
    const __half* __restrict__ Q, const __half* __restrict__ K,
    const __half* __restrict__ V, __half* __restrict__ O)
{
    const int qt = (SS / 128 - 1) - blockIdx.x;
    const int h  = blockIdx.y;
    const int b  = blockIdx.z;
    const int tid  = threadIdx.x;
    const int warp = tid >> 5;
    const int lane = tid & 31;
    const int g    = lane >> 2;
    const int t    = lane & 3;
    const int wm   = warp << 5;

    extern __shared__ __half smh[];
    __half* Qs = smh;                    // [128][HP]
    __half* Ks = Qs + 128 * HP;          // [2][64][HP]
    __half* Vs = Ks + 2 * 64 * HP;       // [2][64][HP]
    __half* Ps = Vs + 2 * 64 * HP;       // [128][HP]

    const uint32_t qsb = smem_u32(Qs);
    const uint32_t ksbase = smem_u32(Ks);
    const uint32_t vsbase = smem_u32(Vs);
    const uint32_t psb = smem_u32(Ps);

    // ldmatrix/stmatrix per-lane offsets
    const int lj = lane >> 3, lr = lane & 7;
    uint32_t moff[2], koff[4];
#pragma unroll
    for (int mi = 0; mi < 2; mi++)
        moff[mi] = (uint32_t)(((wm + (mi << 4) + ((lj & 1) << 3) + lr) * HP
                               + ((lj >> 1) << 3)) * 2);
#pragma unroll
    for (int np = 0; np < 4; np++)
        koff[np] = (uint32_t)((((np << 4) + ((lj & 1) << 3) + lr) * HP
                               + ((lj >> 1) << 3)) * 2);

    const int vrow = ((lane >> 3) & 1) * 8 + (lane & 7);
    const int vcol = (lane >> 4) * 8;

    const __half* Kh0 = K + ((size_t)(b * SS)) * DD + h * DKH;
    const __half* Vh0 = V + ((size_t)(b * SS)) * DD + h * DKH;

    auto load_kv = [&](int kt, int buf) {
        const __half* Kb = Kh0 + (size_t)(kt * 64) * DD;
        const __half* Vb = Vh0 + (size_t)(kt * 64) * DD;
        const uint32_t kb = ksbase + buf * 64 * ROWB;
        const uint32_t vb = vsbase + buf * 64 * ROWB;
#pragma unroll
        for (int i = 0; i < 4; i++) {
            int e = i * 128 + tid;
            int r = e >> 3;
            int c8 = e & 7;
            cpa16(kb + r * ROWB + (c8 << 4), Kb + (size_t)r * DD + (c8 << 3));
            cpa16(vb + r * ROWB + (c8 << 4), Vb + (size_t)r * DD + (c8 << 3));
        }
        cpa_commit();
    };

    // ---- load Q tile ----
    const __half* Qb = Q + ((size_t)(b * SS + qt * 128)) * DD + h * DKH;
#pragma unroll
    for (int i = 0; i < 8; i++) {
        int e = i * 128 + tid;
        int r = e >> 3;
        int c8 = e & 7;
        *(uint4*)&Qs[r * HP + (c8 << 3)] = *(const uint4*)(Qb + (size_t)r * DD + (c8 << 3));
    }

    load_kv(0, 0);

    float m_i[2][2], l_i[2][2], co[2][8][4];
#pragma unroll
    for (int mi = 0; mi < 2; mi++)
#pragma unroll
        for (int hh = 0; hh < 2; hh++) { m_i[mi][hh] = -INFINITY; l_i[mi][hh] = 0.f; }
#pragma unroll
    for (int mi = 0; mi < 2; mi++)
#pragma unroll
        for (int ni = 0; ni < 8; ni++)
#pragma unroll
            for (int j = 0; j < 4; j++) co[mi][ni][j] = 0.f;

    const uint32_t bones = 0x3C003C00u;  // half2(1,1)
    const int ktmax = 2 * qt + 1;

    for (int kt = 0; kt <= ktmax; kt++) {
        __syncthreads();
        if (kt < ktmax) {
            load_kv(kt + 1, (kt + 1) & 1);
            cpa_wait<1>();
        } else {
            cpa_wait<0>();
        }
        __syncthreads();

        const uint32_t ktile = ksbase + (kt & 1) * 64 * ROWB;
        const uint32_t vtile = vsbase + (kt & 1) * 64 * ROWB;

        // ---- S = Q K^T (pre-scaled via wq) ----
        float cs[2][8][4];
#pragma unroll
        for (int mi = 0; mi < 2; mi++)
#pragma unroll
            for (int ni = 0; ni < 8; ni++)
#pragma unroll
                for (int j = 0; j < 4; j++) cs[mi][ni][j] = 0.f;

#pragma unroll
        for (int ks = 0; ks < 4; ks++) {
            uint32_t a[2][4], bf[8][2];
#pragma unroll
            for (int mi = 0; mi < 2; mi++)
                ldsm4(a[mi][0], a[mi][1], a[mi][2], a[mi][3],
                      qsb + moff[mi] + ks * 32);
#pragma unroll
            for (int np = 0; np < 4; np++)
                ldsm4(bf[2*np][0], bf[2*np+1][0], bf[2*np][1], bf[2*np+1][1],
                      ktile + koff[np] + ks * 32);
#pragma unroll
            for (int mi = 0; mi < 2; mi++)
#pragma unroll
                for (int ni = 0; ni < 8; ni++)
                    mma_f16(cs[mi][ni], a[mi], bf[ni]);
        }

        // ---- causal mask (only last two tiles) ----
        if (kt >= 2 * qt) {
#pragma unroll
            for (int mi = 0; mi < 2; mi++)
#pragma unroll
                for (int ni = 0; ni < 8; ni++)
#pragma unroll
                    for (int j = 0; j < 4; j++) {
                        int row = qt * 128 + wm + (mi << 4) + g + ((j >> 1) << 3);
                        int col = kt * 64 + (ni << 3) + (t << 1) + (j & 1);
                        if (col > row) cs[mi][ni][j] = -1e9f;
                    }
        }

        // ---- online softmax: max + alpha ----
        float ml[2][2], al[2][2];
#pragma unroll
        for (int mi = 0; mi < 2; mi++)
#pragma unroll
            for (int hh = 0; hh < 2; hh++) {
                float mx = -INFINITY;
#pragma unroll
                for (int ni = 0; ni < 8; ni++)
                    mx = fmaxf(mx, fmaxf(cs[mi][ni][2*hh], cs[mi][ni][2*hh+1]));
                mx = fmaxf(mx, __shfl_xor_sync(0xffffffffu, mx, 1));
                mx = fmaxf(mx, __shfl_xor_sync(0xffffffffu, mx, 2));
                float m2 = fmaxf(m_i[mi][hh], mx);
                al[mi][hh] = __expf(m_i[mi][hh] - m2);
                m_i[mi][hh] = m2;
                ml[mi][hh] = m2 * L2E;
            }
#pragma unroll
        for (int mi = 0; mi < 2; mi++)
#pragma unroll
            for (int ni = 0; ni < 8; ni++)
#pragma unroll
                for (int j = 0; j < 4; j++)
                    co[mi][ni][j] *= al[mi][j >> 1];

        // ---- P = exp2(S·log2e − m·log2e) in half; stmatrix to smem ----
#pragma unroll
        for (int mi = 0; mi < 2; mi++) {
#pragma unroll
            for (int np = 0; np < 4; np++) {
                int ni = 2 * np, ni1 = 2 * np + 1;
                uint32_t r0 = ex2h2(pkh2(fmaf(cs[mi][ni ][0], L2E, -ml[mi][0]),
                                         fmaf(cs[mi][ni ][1], L2E, -ml[mi][0])));
                uint32_t r1 = ex2h2(pkh2(fmaf(cs[mi][ni ][2], L2E, -ml[mi][1]),
                                         fmaf(cs[mi][ni ][3], L2E, -ml[mi][1])));
                uint32_t r2 = ex2h2(pkh2(fmaf(cs[mi][ni1][0], L2E, -ml[mi][0]),
                                         fmaf(cs[mi][ni1][1], L2E, -ml[mi][0])));
                uint32_t r3 = ex2h2(pkh2(fmaf(cs[mi][ni1][2], L2E, -ml[mi][1]),
                                         fmaf(cs[mi][ni1][3], L2E, -ml[mi][1])));
                stsm4(psb + moff[mi] + np * 32, r0, r1, r2, r3);
            }
        }
        __syncwarp();

        // ---- O += P @ V  and  l-rowsum via MMA with ones ----
        float csum[2][4];
#pragma unroll
        for (int mi = 0; mi < 2; mi++)
#pragma unroll
            for (int j = 0; j < 4; j++) csum[mi][j] = 0.f;

#pragma unroll
        for (int ks = 0; ks < 4; ks++) {
            uint32_t a[2][4], bf[8][2];
#pragma unroll
            for (int mi = 0; mi < 2; mi++)
                ldsm4(a[mi][0], a[mi][1], a[mi][2], a[mi][3],
                      psb + moff[mi] + ks * 32);
#pragma unroll
            for (int nn = 0; nn < 4; nn++) {
                uint32_t addr = vtile + ((ks << 4) + vrow) * ROWB + ((nn << 4) + vcol) * 2;
                ldsm4t(bf[2*nn][0], bf[2*nn][1], bf[2*nn+1][0], bf[2*nn+1][1], addr);
            }
#pragma unroll
            for (int mi = 0; mi < 2; mi++) {
                uint32_t bo[2] = {bones, bones};
                mma_f16(csum[mi], a[mi], bo);
#pragma unroll
                for (int ni = 0; ni < 8; ni++)
                    mma_f16(co[mi][ni], a[mi], bf[ni]);
            }
        }

#pragma unroll
        for (int mi = 0; mi < 2; mi++)
#pragma unroll
            for (int hh = 0; hh < 2; hh++)
                l_i[mi][hh] = l_i[mi][hh] * al[mi][hh] + csum[mi][2*hh];
    }

    // ---- epilogue ----
#pragma unroll
    for (int mi = 0; mi < 2; mi++)
#pragma unroll
        for (int hh = 0; hh < 2; hh++) {
            float inv = 1.f / l_i[mi][hh];
            int row = qt * 128 + wm + (mi << 4) + g + (hh << 3);
            __half* ob = O + ((size_t)(b * SS + row)) * DD + h * DKH;
#pragma unroll
            for (int ni = 0; ni < 8; ni++) {
                int col = (ni << 3) + (t << 1);
                *(uint32_t*)(ob + col) = pkh2(co[mi][ni][2*hh] * inv,
                                              co[mi][ni][2*hh+1] * inv);
            }
        }
}

// =============================================================================
// Launch
// =============================================================================
extern "C" void kernel_launch(void* const* d_in, const int* in_sizes, int n_in,
                              void* d_out, int out_size)
{
    const float* q  = (const float*)d_in[1];
    const float* k  = (const float*)d_in[2];
    const float* v  = (const float*)d_in[3];
    const float* wq = (const float*)d_in[5];
    const float* bq = (const float*)d_in[6];
    const float* wk = (const float*)d_in[7];
    const float* bk = (const float*)d_in[8];
    const float* wv = (const float*)d_in[9];
    const float* bv = (const float*)d_in[10];
    const float* wo = (const float*)d_in[11];
    const float* bo = (const float*)d_in[12];
    float* out = (float*)d_out;

    __half *aq, *ak, *av, *qh, *kh, *vh, *aoh, *wtq, *wtk, *wtv, *wto;
    cudaGetSymbolAddress((void**)&aq,  g_Aq);
    cudaGetSymbolAddress((void**)&ak,  g_Ak);
    cudaGetSymbolAddress((void**)&av,  g_Av);
    cudaGetSymbolAddress((void**)&qh,  g_Qh);
    cudaGetSymbolAddress((void**)&kh,  g_Kh);
    cudaGetSymbolAddress((void**)&vh,  g_Vh);
    cudaGetSymbolAddress((void**)&aoh, g_AOh);
    cudaGetSymbolAddress((void**)&wtq, g_Wq);
    cudaGetSymbolAddress((void**)&wtk, g_Wk);
    cudaGetSymbolAddress((void**)&wtv, g_Wv);
    cudaGetSymbolAddress((void**)&wto, g_Wo);

    cudaFuncSetAttribute(flash_f16_kernel,
                         cudaFuncAttributeMaxDynamicSharedMemorySize, ATT_SMEM);
    cudaFuncSetAttribute(gemm_qkv_f16,
                         cudaFuncAttributeMaxDynamicSharedMemorySize, G_SMEM);
    cudaFuncSetAttribute(gemm_o_f16,
                         cudaFuncAttributeMaxDynamicSharedMemorySize, G_SMEM);

    // ---- prepass (2 launches) ----
    const int nA4 = MTOT * DD / 4;
    act_conv_kernel<<<dim3(nA4 / 256, 3), 256>>>(q, k, v, aq, ak, av);
    wt_trans_kernel<<<dim3(DD / 32, DD / 32, 4), dim3(32, 8)>>>(
        wq, wk, wv, wo, wtq, wtk, wtv, wto);

    // ---- fused QKV projections ----
    dim3 gblk(256);
    dim3 gqkv(DD / 128, MTOT / 128, 3);   // (8, 64, 3)
    gemm_qkv_f16<<<gqkv, gblk, G_SMEM>>>(aq, ak, av, wtq, wtk, wtv,
                                         bq, bk, bv, qh, kh, vh);

    // ---- attention ----
    dim3 agrid(SS / 128, HH, BB);         // (16, 16, 4)
    flash_f16_kernel<<<agrid, dim3(128), ATT_SMEM>>>(qh, kh, vh, aoh);

    // ---- output projection (fp32 out) ----
    dim3 go(DD / 128, MTOT / 128);
    gemm_o_f16<<<go, gblk, G_SMEM>>>(aoh, wto, bo, out);
}